// round 11
// baseline (speedup 1.0000x reference)
#include <cuda_runtime.h>
#include <cuda_bf16.h>
#include <cuda_fp16.h>
#include <cstdint>

// ---------------------------------------------------------------------------
// Problem constants
// ---------------------------------------------------------------------------
#define BATCH   4
#define SEQ     2048
#define DMODEL  512
#define DHID    2048
#define NHEADS  2
#define GSZ     256
#define MTOT    (BATCH * SEQ)       // 8192

// ---------------------------------------------------------------------------
// Scratch (device globals)
// ---------------------------------------------------------------------------
__device__ float g_q  [MTOT * DMODEL];
__device__ float g_k  [MTOT * DMODEL];
__device__ float g_v  [MTOT * DMODEL];
__device__ float g_att[MTOT * DMODEL];
__device__ float g_x  [MTOT * DMODEL];
__device__ float g_y  [MTOT * DMODEL];
__device__ float g_css[MTOT * DMODEL];
__device__ float g_cqq[MTOT * DMODEL];

// fp16 operand buffers (hi / lo split for activations, hi-only for weights)
__device__ __half g_wqf[3*DMODEL*DMODEL];
__device__ __half g_wkf[3*DMODEL*DMODEL];
__device__ __half g_wvf[3*DMODEL*DMODEL];
__device__ __half g_w1f[3*DHID*DMODEL];
__device__ __half g_w2f[3*DMODEL*DHID];
__device__ __half g_fmh[MTOT*DMODEL], g_fml[MTOT*DMODEL];
__device__ __half g_fsh[MTOT*DMODEL], g_fsl[MTOT*DMODEL];
__device__ __half g_fqh[MTOT*DMODEL], g_fql[MTOT*DMODEL];
__device__ __half g_cssh[MTOT*DMODEL], g_cssl[MTOT*DMODEL];
__device__ __half g_cqqh[MTOT*DMODEL], g_cqql[MTOT*DMODEL];
__device__ __half g_xh[MTOT*DMODEL],  g_xl[MTOT*DMODEL];
__device__ __half g_hh[MTOT*DHID],    g_hl[MTOT*DHID];

// ---------------------------------------------------------------------------
// helpers
// ---------------------------------------------------------------------------
__device__ __forceinline__ uint32_t sptr(const void* p) {
    return (uint32_t)__cvta_generic_to_shared(p);
}
__device__ __forceinline__ void ldm4(uint32_t a, uint32_t& r0, uint32_t& r1,
                                     uint32_t& r2, uint32_t& r3) {
    asm volatile("ldmatrix.sync.aligned.m8n8.x4.shared.b16 {%0,%1,%2,%3},[%4];"
                 : "=r"(r0), "=r"(r1), "=r"(r2), "=r"(r3) : "r"(a));
}
__device__ __forceinline__ void mma_bf16(float c[4], const uint32_t a[4],
                                         const uint32_t b[2]) {
    asm volatile(
        "mma.sync.aligned.m16n8k16.row.col.f32.bf16.bf16.f32 "
        "{%0,%1,%2,%3},{%4,%5,%6,%7},{%8,%9},{%0,%1,%2,%3};"
        : "+f"(c[0]), "+f"(c[1]), "+f"(c[2]), "+f"(c[3])
        : "r"(a[0]), "r"(a[1]), "r"(a[2]), "r"(a[3]), "r"(b[0]), "r"(b[1]));
}
__device__ __forceinline__ void mma_f16(float c[4], const uint32_t a[4],
                                        const uint32_t b[2]) {
    asm volatile(
        "mma.sync.aligned.m16n8k16.row.col.f32.f16.f16.f32 "
        "{%0,%1,%2,%3},{%4,%5,%6,%7},{%8,%9},{%0,%1,%2,%3};"
        : "+f"(c[0]), "+f"(c[1]), "+f"(c[2]), "+f"(c[3])
        : "r"(a[0]), "r"(a[1]), "r"(a[2]), "r"(a[3]), "r"(b[0]), "r"(b[1]));
}
__device__ __forceinline__ float e2(float x) {
    float y; asm("ex2.approx.ftz.f32 %0,%1;" : "=f"(y) : "f"(x)); return y;
}
__device__ __forceinline__ uint32_t packbf(float a, float b) {
    const __nv_bfloat162 t = __float22bfloat162_rn(make_float2(a, b));
    return *reinterpret_cast<const uint32_t*>(&t);
}
__device__ __forceinline__ void split2h(float v, __half& h, __half& l) {
    h = __float2half_rn(v);
    l = __float2half_rn(v - __half2float(h));
}
__device__ __forceinline__ void cpa16(uint32_t s, const void* g) {
    asm volatile("cp.async.cg.shared.global [%0],[%1],16;" :: "r"(s), "l"(g));
}
__device__ __forceinline__ void cpa_commit() {
    asm volatile("cp.async.commit_group;");
}
template <int N>
__device__ __forceinline__ void cpa_wait() {
    asm volatile("cp.async.wait_group %0;" :: "n"(N));
}

// ---------------------------------------------------------------------------
// fused input split: {Fm, Fs, Fq} fp32 -> fp16 (hi, lo)
// ---------------------------------------------------------------------------
#define SEG4 (MTOT * DMODEL / 4)       // 1,048,576 float4 per input

__global__ __launch_bounds__(256)
void split_in_kernel(const float* __restrict__ Fm, const float* __restrict__ Fs,
                     const float* __restrict__ Fq)
{
    const int i = blockIdx.x * 256 + threadIdx.x;      // 0 .. 3*SEG4-1
    if (i >= 3 * SEG4) return;
    const int seg = i / SEG4;
    const int off = i - seg * SEG4;
    const float* src = (seg == 0) ? Fm : (seg == 1) ? Fs : Fq;
    __half* dh = (seg == 0) ? g_fmh : (seg == 1) ? g_fsh : g_fqh;
    __half* dl = (seg == 0) ? g_fml : (seg == 1) ? g_fsl : g_fql;
    const float4 v = *(const float4*)(src + (size_t)off * 4);
    __half h0, h1, h2, h3, l0, l1, l2, l3;
    split2h(v.x, h0, l0); split2h(v.y, h1, l1);
    split2h(v.z, h2, l2); split2h(v.w, h3, l3);
    *(__half2*)(dh + (size_t)off * 4)     = __halves2half2(h0, h1);
    *(__half2*)(dh + (size_t)off * 4 + 2) = __halves2half2(h2, h3);
    *(__half2*)(dl + (size_t)off * 4)     = __halves2half2(l0, l1);
    *(__half2*)(dl + (size_t)off * 4 + 2) = __halves2half2(l2, l3);
}

// ---------------------------------------------------------------------------
// fused weight convert: {Wq, Wk, Wv, w1, w2} fp32 -> fp16 (hi only)
// ---------------------------------------------------------------------------
#define WQ4 (3 * DMODEL * DMODEL / 4)     // 196,608 float4 each for wq/wk/wv
#define W14 (3 * DHID * DMODEL / 4)       // 786,432 float4 for w1 (and w2)
#define WTOT4 (3 * WQ4 + 2 * W14)

__global__ __launch_bounds__(256)
void conv_w_kernel(const float* __restrict__ Wq, const float* __restrict__ Wk,
                   const float* __restrict__ Wv, const float* __restrict__ w1,
                   const float* __restrict__ w2)
{
    const int i = blockIdx.x * 256 + threadIdx.x;
    if (i >= WTOT4) return;
    const float* src; __half* dst; int off;
    if (i < WQ4)               { src = Wq; dst = g_wqf; off = i; }
    else if (i < 2 * WQ4)      { src = Wk; dst = g_wkf; off = i - WQ4; }
    else if (i < 3 * WQ4)      { src = Wv; dst = g_wvf; off = i - 2 * WQ4; }
    else if (i < 3 * WQ4 + W14){ src = w1; dst = g_w1f; off = i - 3 * WQ4; }
    else                       { src = w2; dst = g_w2f; off = i - 3 * WQ4 - W14; }
    const float4 v = *(const float4*)(src + (size_t)off * 4);
    *(__half2*)(dst + (size_t)off * 4)     = __floats2half2_rn(v.x, v.y);
    *(__half2*)(dst + (size_t)off * 4 + 2) = __floats2half2_rn(v.z, v.w);
}

// ---------------------------------------------------------------------------
// fp16 2-pass split GEMM:  C = epi( (Ah+Al)[M,K] @ Bh[N,K]^T )
// 128x128x32 CTA tile, 4 warps (64x64 each), cp.async double-buffered.
// Error: dropped A*Bl term ~2^-11 relative.
// OUT: 0 -> fp32 C;  1 -> relu + fp16 split (Ch, Cl)
// ---------------------------------------------------------------------------
#define TBM 128
#define TBN 128
#define TBK 32
#define TAS 40
#define REGB  (TBM * TAS * 2)      // 10240 bytes per matrix region
#define BUFSZ (3 * REGB)           // Ah | Al | Bh = 30720
#define GEMM_SMEM (2 * BUFSZ)      // 61440 -> 2 CTAs/SM

extern __shared__ char gsm[];

template <int OUT>
__global__ __launch_bounds__(128, 2)
void gemm_fp16(const __half* __restrict__ Agh, const __half* __restrict__ Agl,
               const __half* __restrict__ Bgh,
               float* __restrict__ C, __half* __restrict__ Ch,
               __half* __restrict__ Cl, int M, int N, int K)
{
    const int tid  = threadIdx.x;
    const int lane = tid & 31;
    const int wid  = tid >> 5;
    const int wm   = wid & 1;        // 2 m-warps * 64 rows
    const int wn   = wid >> 1;       // 2 n-warps * 64 cols
    const int bm   = blockIdx.y * TBM;
    const int bn   = blockIdx.x * TBN;

    const uint32_t sbase = sptr(gsm);

    // loader: 512 16B-chunks per region, 4 per thread per region
    auto load_tile = [&](int buf, int k0) {
        const uint32_t b = sbase + buf * BUFSZ;
#pragma unroll
        for (int j = 0; j < 4; ++j) {
            const int c = tid + j * 128;           // 0..511
            const int row = c >> 2, kc = (c & 3) << 3;
            const uint32_t so = (uint32_t)(row * TAS + kc) * 2;
            const size_t goA = (size_t)(bm + row) * K + k0 + kc;
            const size_t goB = (size_t)(bn + row) * K + k0 + kc;
            cpa16(b + so,            Agh + goA);
            cpa16(b + REGB + so,     Agl + goA);
            cpa16(b + 2 * REGB + so, Bgh + goB);
        }
        cpa_commit();
    };

    float c[4][8][4];
#pragma unroll
    for (int mi = 0; mi < 4; ++mi)
#pragma unroll
        for (int ni = 0; ni < 8; ++ni)
#pragma unroll
            for (int e = 0; e < 4; ++e) c[mi][ni][e] = 0.f;

    // fragment lane geometry (validated pattern)
    const int lmA = lane & 15;
    const int lkA = (lane >> 4) << 3;
    const int lnB = ((lane >> 4) & 1) * 8 + (lane & 7);
    const int lkB = ((lane >> 3) & 1) * 8;
    const uint32_t relA = (uint32_t)((wm * 64 + lmA) * TAS + lkA) * 2;
    const uint32_t relB = (uint32_t)((wn * 64 + lnB) * TAS + lkB) * 2;

    const int niter = K / TBK;
    load_tile(0, 0);

    for (int it = 0; it < niter; ++it) {
        const int cur = it & 1;
        if (it + 1 < niter) { load_tile(cur ^ 1, (it + 1) * TBK); cpa_wait<1>(); }
        else cpa_wait<0>();
        __syncthreads();

        const uint32_t b = sbase + cur * BUFSZ;
        const uint32_t aAh = b + relA, aAl = b + REGB + relA;
        const uint32_t aBh = b + 2 * REGB + relB;

#pragma unroll
        for (int ks = 0; ks < 2; ++ks) {
            const uint32_t ko = ks * 32;     // 16 fp16 = 32 bytes
            uint32_t bhf[8][2];
#pragma unroll
            for (int p = 0; p < 4; ++p) {
                ldm4(aBh + p * (16 * TAS * 2) + ko,
                     bhf[2*p][0], bhf[2*p][1], bhf[2*p+1][0], bhf[2*p+1][1]);
            }
#pragma unroll
            for (int mi = 0; mi < 4; ++mi) {
                uint32_t ah[4], al[4];
                ldm4(aAh + mi * (16 * TAS * 2) + ko, ah[0], ah[1], ah[2], ah[3]);
                ldm4(aAl + mi * (16 * TAS * 2) + ko, al[0], al[1], al[2], al[3]);
#pragma unroll
                for (int ni = 0; ni < 8; ++ni) mma_f16(c[mi][ni], ah, bhf[ni]);
#pragma unroll
                for (int ni = 0; ni < 8; ++ni) mma_f16(c[mi][ni], al, bhf[ni]);
            }
        }
        __syncthreads();
    }

    // epilogue
#pragma unroll
    for (int mi = 0; mi < 4; ++mi) {
        const int row0 = bm + wm * 64 + mi * 16 + (lane >> 2);
#pragma unroll
        for (int ni = 0; ni < 8; ++ni) {
            const int col = bn + wn * 64 + ni * 8 + ((lane & 3) << 1);
            float v0 = c[mi][ni][0], v1 = c[mi][ni][1];
            float v2 = c[mi][ni][2], v3 = c[mi][ni][3];
            if (OUT == 0) {
                float2 a; a.x = v0; a.y = v1;
                float2 bq; bq.x = v2; bq.y = v3;
                *(float2*)&C[(size_t)row0 * N + col]       = a;
                *(float2*)&C[(size_t)(row0 + 8) * N + col] = bq;
            } else {
                v0 = fmaxf(v0, 0.f); v1 = fmaxf(v1, 0.f);
                v2 = fmaxf(v2, 0.f); v3 = fmaxf(v3, 0.f);
                __half h0, h1, h2, h3, l0, l1, l2, l3;
                split2h(v0, h0, l0); split2h(v1, h1, l1);
                split2h(v2, h2, l2); split2h(v3, h3, l3);
                *(__half2*)&Ch[(size_t)row0 * N + col]       = __halves2half2(h0, h1);
                *(__half2*)&Cl[(size_t)row0 * N + col]       = __halves2half2(l0, l1);
                *(__half2*)&Ch[(size_t)(row0 + 8) * N + col] = __halves2half2(h2, h3);
                *(__half2*)&Cl[(size_t)(row0 + 8) * N + col] = __halves2half2(l2, l3);
            }
        }
    }
}

// ---------------------------------------------------------------------------
// Tensor-core flash attention (mma.sync bf16, validated @336us)
// ---------------------------------------------------------------------------
#define FM  64
#define FN  64
#define FQS 264
#define VTS 72
#define FA_SMEM_BYTES ((FM*FQS + FN*FQS + GSZ*VTS) * 2)

extern __shared__ char fa_raw[];

__global__ __launch_bounds__(128, 2)
void flash_tc(const float* __restrict__ Q, const float* __restrict__ K,
              const float* __restrict__ V, float* __restrict__ O)
{
    __nv_bfloat16* Qs = (__nv_bfloat16*)fa_raw;
    __nv_bfloat16* Ks = Qs + FM * FQS;
    __nv_bfloat16* Vt = Ks + FN * FQS;

    const int tid  = threadIdx.x;
    const int lane = tid & 31;
    const int w    = tid >> 5;
    const int qbase = blockIdx.x * FM;
    const int h = blockIdx.y, b = blockIdx.z;
    const size_t bstride = (size_t)SEQ * DMODEL;
    const float* Qb = Q + b * bstride + h * GSZ;
    const float* Kb = K + b * bstride + h * GSZ;
    const float* Vb = V + b * bstride + h * GSZ;

    const int lmA = lane & 15;
    const int lkA = (lane >> 4) << 3;
    const int lnB = ((lane >> 4) & 1) * 8 + (lane & 7);
    const int lkB = ((lane >> 3) & 1) * 8;

    const uint32_t aQ = sptr(Qs) + (uint32_t)((w * 16 + lmA) * FQS + lkA) * 2;
    const uint32_t aK = sptr(Ks) + (uint32_t)(lnB * FQS + lkB) * 2;
    const uint32_t aV = sptr(Vt) + (uint32_t)(lnB * VTS + lkB) * 2;

    const float qscale = 0.0625f * 1.4426950408889634f;
    for (int j = 0; j < 32; ++j) {
        const int idx = tid + j * 128;
        const int row = idx >> 6, f4 = idx & 63;
        const float4 v = *(const float4*)(Qb + (size_t)(qbase + row) * DMODEL + f4 * 4);
        __nv_bfloat16* p = Qs + row * FQS + f4 * 4;
        *(__nv_bfloat162*)(p)     = __float22bfloat162_rn(make_float2(v.x * qscale, v.y * qscale));
        *(__nv_bfloat162*)(p + 2) = __float22bfloat162_rn(make_float2(v.z * qscale, v.w * qscale));
    }

    float mA = -1e30f, mB = -1e30f, lA = 0.f, lB = 0.f;
    float o[32][4];
#pragma unroll
    for (int f = 0; f < 32; ++f)
#pragma unroll
        for (int e = 0; e < 4; ++e) o[f][e] = 0.f;

    const int vkcol = tid & 63;
    const int vdch  = tid >> 6;

    for (int kb = 0; kb < SEQ; kb += FN) {
        __syncthreads();
        for (int j = 0; j < 32; ++j) {
            const int idx = tid + j * 128;
            const int row = idx >> 6, f4 = idx & 63;
            const float4 v = *(const float4*)(Kb + (size_t)(kb + row) * DMODEL + f4 * 4);
            __nv_bfloat16* p = Ks + row * FQS + f4 * 4;
            *(__nv_bfloat162*)(p)     = __float22bfloat162_rn(make_float2(v.x, v.y));
            *(__nv_bfloat162*)(p + 2) = __float22bfloat162_rn(make_float2(v.z, v.w));
        }
        {
            const float* vsrc = Vb + (size_t)(kb + vkcol) * DMODEL + vdch * 128;
#pragma unroll
            for (int j = 0; j < 32; ++j) {
                const float4 v = *(const float4*)(vsrc + j * 4);
                const int d = vdch * 128 + j * 4;
                Vt[(d + 0) * VTS + vkcol] = __float2bfloat16(v.x);
                Vt[(d + 1) * VTS + vkcol] = __float2bfloat16(v.y);
                Vt[(d + 2) * VTS + vkcol] = __float2bfloat16(v.z);
                Vt[(d + 3) * VTS + vkcol] = __float2bfloat16(v.w);
            }
        }
        __syncthreads();

        float s[8][4];
#pragma unroll
        for (int f = 0; f < 8; ++f)
#pragma unroll
            for (int e = 0; e < 4; ++e) s[f][e] = 0.f;

#pragma unroll
        for (int ks = 0; ks < 16; ++ks) {
            uint32_t af[4];
            ldm4(aQ + ks * 32, af[0], af[1], af[2], af[3]);
#pragma unroll
            for (int g = 0; g < 4; ++g) {
                uint32_t b0[2], b1[2];
                ldm4(aK + (uint32_t)(g * 16 * FQS) * 2 + ks * 32,
                     b0[0], b0[1], b1[0], b1[1]);
                mma_bf16(s[2 * g],     af, b0);
                mma_bf16(s[2 * g + 1], af, b1);
            }
        }

        float mxA = -1e30f, mxB = -1e30f;
#pragma unroll
        for (int f = 0; f < 8; ++f) {
            mxA = fmaxf(mxA, fmaxf(s[f][0], s[f][1]));
            mxB = fmaxf(mxB, fmaxf(s[f][2], s[f][3]));
        }
        mxA = fmaxf(mxA, __shfl_xor_sync(0xffffffffu, mxA, 1));
        mxA = fmaxf(mxA, __shfl_xor_sync(0xffffffffu, mxA, 2));
        mxB = fmaxf(mxB, __shfl_xor_sync(0xffffffffu, mxB, 1));
        mxB = fmaxf(mxB, __shfl_xor_sync(0xffffffffu, mxB, 2));
        const float mnA = fmaxf(mA, mxA);
        const float mnB = fmaxf(mB, mxB);
        float sumA = 0.f, sumB = 0.f;
#pragma unroll
        for (int f = 0; f < 8; ++f) {
            s[f][0] = e2(s[f][0] - mnA); s[f][1] = e2(s[f][1] - mnA);
            s[f][2] = e2(s[f][2] - mnB); s[f][3] = e2(s[f][3] - mnB);
            sumA += s[f][0] + s[f][1];
            sumB += s[f][2] + s[f][3];
        }
        sumA += __shfl_xor_sync(0xffffffffu, sumA, 1);
        sumA += __shfl_xor_sync(0xffffffffu, sumA, 2);
        sumB += __shfl_xor_sync(0xffffffffu, sumB, 1);
        sumB += __shfl_xor_sync(0xffffffffu, sumB, 2);
        const float ccA = e2(mA - mnA);
        const float ccB = e2(mB - mnB);
        lA = lA * ccA + sumA; mA = mnA;
        lB = lB * ccB + sumB; mB = mnB;

#pragma unroll
        for (int f = 0; f < 32; ++f) {
            o[f][0] *= ccA; o[f][1] *= ccA;
            o[f][2] *= ccB; o[f][3] *= ccB;
        }

#pragma unroll
        for (int kf = 0; kf < 4; ++kf) {
            uint32_t ap[4];
            ap[0] = packbf(s[2 * kf][0],     s[2 * kf][1]);
            ap[1] = packbf(s[2 * kf][2],     s[2 * kf][3]);
            ap[2] = packbf(s[2 * kf + 1][0], s[2 * kf + 1][1]);
            ap[3] = packbf(s[2 * kf + 1][2], s[2 * kf + 1][3]);
#pragma unroll
            for (int g = 0; g < 16; ++g) {
                uint32_t b0[2], b1[2];
                ldm4(aV + (uint32_t)(g * 16 * VTS) * 2 + kf * 32,
                     b0[0], b0[1], b1[0], b1[1]);
                mma_bf16(o[2 * g],     ap, b0);
                mma_bf16(o[2 * g + 1], ap, b1);
            }
        }
    }

    const float liA = 1.f / lA;
    const float liB = 1.f / lB;
    const int rowA = qbase + w * 16 + (lane >> 2);
    float* Ob = O + b * bstride + h * GSZ;
#pragma unroll
    for (int f = 0; f < 32; ++f) {
        const int col = f * 8 + ((lane & 3) << 1);
        float2 rA; rA.x = o[f][0] * liA; rA.y = o[f][1] * liA;
        float2 rB; rB.x = o[f][2] * liB; rB.y = o[f][3] * liB;
        *(float2*)&Ob[(size_t)rowA * DMODEL + col]       = rA;
        *(float2*)&Ob[(size_t)(rowA + 8) * DMODEL + col] = rB;
    }
}

// ---------------------------------------------------------------------------
// out = LayerNorm(X + R); optionally emit fp16 (hi, lo) split
// ---------------------------------------------------------------------------
__global__ __launch_bounds__(128)
void add_ln_kernel(const float* __restrict__ X, const float* __restrict__ R,
                   const float* __restrict__ g, const float* __restrict__ bt,
                   float eps, float* __restrict__ out,
                   __half* __restrict__ oh, __half* __restrict__ ol,
                   int doSplit)
{
    const int row = blockIdx.x;
    const int tid = threadIdx.x;
    float4 v = *(const float4*)(X + (size_t)row * DMODEL + tid * 4);
    const float4 rr = *(const float4*)(R + (size_t)row * DMODEL + tid * 4);
    v.x += rr.x; v.y += rr.y; v.z += rr.z; v.w += rr.w;
    float s  = v.x + v.y + v.z + v.w;
    float sq = v.x * v.x + v.y * v.y + v.z * v.z + v.w * v.w;
#pragma unroll
    for (int off = 16; off; off >>= 1) {
        s  += __shfl_xor_sync(0xffffffffu, s,  off);
        sq += __shfl_xor_sync(0xffffffffu, sq, off);
    }
    __shared__ float ssum[4], ssq[4];
    const int w = tid >> 5, l = tid & 31;
    if (l == 0) { ssum[w] = s; ssq[w] = sq; }
    __syncthreads();
    s  = ssum[0] + ssum[1] + ssum[2] + ssum[3];
    sq = ssq[0]  + ssq[1]  + ssq[2]  + ssq[3];
    const float mean = s * (1.f / DMODEL);
    const float var  = sq * (1.f / DMODEL) - mean * mean;
    const float rstd = rsqrtf(var + eps);
    const float4 gg = *(const float4*)(g  + tid * 4);
    const float4 bb = *(const float4*)(bt + tid * 4);
    float4 r;
    r.x = (v.x - mean) * rstd * gg.x + bb.x;
    r.y = (v.y - mean) * rstd * gg.y + bb.y;
    r.z = (v.z - mean) * rstd * gg.z + bb.z;
    r.w = (v.w - mean) * rstd * gg.w + bb.w;
    *(float4*)(out + (size_t)row * DMODEL + tid * 4) = r;
    if (doSplit) {
        __half h0, h1, h2, h3, l0, l1, l2, l3;
        split2h(r.x, h0, l0); split2h(r.y, h1, l1);
        split2h(r.z, h2, l2); split2h(r.w, h3, l3);
        const size_t o = (size_t)row * DMODEL + tid * 4;
        *(__half2*)(oh + o)     = __halves2half2(h0, h1);
        *(__half2*)(oh + o + 2) = __halves2half2(h2, h3);
        *(__half2*)(ol + o)     = __halves2half2(l0, l1);
        *(__half2*)(ol + o + 2) = __halves2half2(l2, l3);
    }
}

// ---------------------------------------------------------------------------
// host side
// ---------------------------------------------------------------------------
extern "C" void kernel_launch(void* const* d_in, const int* in_sizes, int n_in,
                              void* d_out, int out_size)
{
    (void)in_sizes; (void)n_in; (void)out_size;
    const float* Fm   = (const float*)d_in[0];
    const float* Fs   = (const float*)d_in[1];
    const float* Fq   = (const float*)d_in[2];
    const float* Wq   = (const float*)d_in[3];
    const float* Wk   = (const float*)d_in[4];
    const float* Wv   = (const float*)d_in[5];
    const float* lng  = (const float*)d_in[6];
    const float* lnb  = (const float*)d_in[7];
    const float* w1   = (const float*)d_in[8];
    const float* w2   = (const float*)d_in[9];
    const float* flg  = (const float*)d_in[10];
    const float* flb  = (const float*)d_in[11];
    float* out = (float*)d_out;

    float *q, *k, *v, *att, *x, *y, *css, *cqq;
    cudaGetSymbolAddress((void**)&q,   g_q);
    cudaGetSymbolAddress((void**)&k,   g_k);
    cudaGetSymbolAddress((void**)&v,   g_v);
    cudaGetSymbolAddress((void**)&att, g_att);
    cudaGetSymbolAddress((void**)&x,   g_x);
    cudaGetSymbolAddress((void**)&y,   g_y);
    cudaGetSymbolAddress((void**)&css, g_css);
    cudaGetSymbolAddress((void**)&cqq, g_cqq);

    __half *wqf, *wkf, *wvf, *w1f, *w2f;
    __half *fmh, *fml, *fsh, *fsl, *fqh, *fql;
    __half *cssh, *cssl, *cqqh, *cqql, *xh, *xl, *hh, *hl;
    cudaGetSymbolAddress((void**)&wqf, g_wqf);
    cudaGetSymbolAddress((void**)&wkf, g_wkf);
    cudaGetSymbolAddress((void**)&wvf, g_wvf);
    cudaGetSymbolAddress((void**)&w1f, g_w1f);
    cudaGetSymbolAddress((void**)&w2f, g_w2f);
    cudaGetSymbolAddress((void**)&fmh, g_fmh); cudaGetSymbolAddress((void**)&fml, g_fml);
    cudaGetSymbolAddress((void**)&fsh, g_fsh); cudaGetSymbolAddress((void**)&fsl, g_fsl);
    cudaGetSymbolAddress((void**)&fqh, g_fqh); cudaGetSymbolAddress((void**)&fql, g_fql);
    cudaGetSymbolAddress((void**)&cssh, g_cssh); cudaGetSymbolAddress((void**)&cssl, g_cssl);
    cudaGetSymbolAddress((void**)&cqqh, g_cqqh); cudaGetSymbolAddress((void**)&cqql, g_cqql);
    cudaGetSymbolAddress((void**)&xh, g_xh);   cudaGetSymbolAddress((void**)&xl, g_xl);
    cudaGetSymbolAddress((void**)&hh, g_hh);   cudaGetSymbolAddress((void**)&hl, g_hl);

    cudaFuncSetAttribute(flash_tc, cudaFuncAttributeMaxDynamicSharedMemorySize,
                         FA_SMEM_BYTES);
    cudaFuncSetAttribute(gemm_fp16<0>, cudaFuncAttributeMaxDynamicSharedMemorySize,
                         GEMM_SMEM);
    cudaFuncSetAttribute(gemm_fp16<1>, cudaFuncAttributeMaxDynamicSharedMemorySize,
                         GEMM_SMEM);

    // fused preprocessing (2 launches)
    split_in_kernel<<<(3 * SEG4 + 255) / 256, 256>>>(Fm, Fs, Fq);
    conv_w_kernel<<<(WTOT4 + 255) / 256, 256>>>(Wq, Wk, Wv, w1, w2);

    const dim3 gp(DMODEL / TBN, MTOT / TBM);   // (4, 64)
    const dim3 gh(DHID / TBN,   MTOT / TBM);   // (16, 64)
    const dim3 ga(SEQ / FM, NHEADS, BATCH);

    auto run_block = [&](int i,
                         const __half* Qh, const __half* Ql,
                         const __half* Kh, const __half* Kl,
                         const __half* Vh, const __half* Vl,
                         const float* Rp, float* op,
                         __half* oph, __half* opl, int splitOut) {
        const size_t wOff  = (size_t)i * DMODEL * DMODEL;
        const size_t w1Off = (size_t)i * DHID * DMODEL;
        gemm_fp16<0><<<gp, 128, GEMM_SMEM>>>(Qh, Ql, wqf + wOff,
                                             q, nullptr, nullptr, MTOT, DMODEL, DMODEL);
        gemm_fp16<0><<<gp, 128, GEMM_SMEM>>>(Kh, Kl, wkf + wOff,
                                             k, nullptr, nullptr, MTOT, DMODEL, DMODEL);
        gemm_fp16<0><<<gp, 128, GEMM_SMEM>>>(Vh, Vl, wvf + wOff,
                                             v, nullptr, nullptr, MTOT, DMODEL, DMODEL);
        flash_tc<<<ga, 128, FA_SMEM_BYTES>>>(q, k, v, att);
        add_ln_kernel<<<MTOT, 128>>>(att, Rp, lng + i * DMODEL, lnb + i * DMODEL,
                                     1e-5f, x, xh, xl, 1);
        gemm_fp16<1><<<gh, 128, GEMM_SMEM>>>(xh, xl, w1f + w1Off,
                                             nullptr, hh, hl, MTOT, DHID, DMODEL);
        gemm_fp16<0><<<gp, 128, GEMM_SMEM>>>(hh, hl, w2f + w1Off,
                                             y, nullptr, nullptr, MTOT, DMODEL, DHID);
        add_ln_kernel<<<MTOT, 128>>>(y, x, flg + i * DMODEL, flb + i * DMODEL,
                                     1e-6f, op, oph, opl, splitOut);
    };

    // css = blk(0, Fs, Fs, Fm, Fm); cqq = blk(1, Fq, Fq, Fq, Fq);
    // csq = blk(2, cqq, Fs, css, css)
    run_block(0, fsh, fsl, fsh, fsl, fmh, fml, Fm, css, cssh, cssl, 1);
    run_block(1, fqh, fql, fqh, fql, fqh, fql, Fq, cqq, cqqh, cqql, 1);
    run_block(2, cqqh, cqql, fsh, fsl, cssh, cssl, css, out, nullptr, nullptr, 0);
}

// round 13
// speedup vs baseline: 1.5880x; 1.5880x over previous
#include <cuda_runtime.h>
#include <cuda_bf16.h>
#include <cstdint>

// ---------------------------------------------------------------------------
// Problem constants
// ---------------------------------------------------------------------------
#define BATCH   4
#define SEQ     2048
#define DMODEL  512
#define DHID    2048
#define NHEADS  2
#define GSZ     256
#define MTOT    (BATCH * SEQ)       // 8192

// softmax scale folded into Wq: 1/sqrt(256) * log2(e)
#define QSC 0.09016994374947424f

// ---------------------------------------------------------------------------
// Scratch (device globals)
// ---------------------------------------------------------------------------
__device__ __nv_bfloat16 g_qb[MTOT * DMODEL];
__device__ __nv_bfloat16 g_kb[MTOT * DMODEL];
__device__ __nv_bfloat16 g_vb[MTOT * DMODEL];
__device__ float g_att[MTOT * DMODEL];
__device__ float g_x  [MTOT * DMODEL];
__device__ float g_y  [MTOT * DMODEL];
__device__ float g_css[MTOT * DMODEL];
__device__ float g_cqq[MTOT * DMODEL];

__device__ __nv_bfloat16 g_wqh[3*DMODEL*DMODEL], g_wql[3*DMODEL*DMODEL];
__device__ __nv_bfloat16 g_wkh[3*DMODEL*DMODEL], g_wkl[3*DMODEL*DMODEL];
__device__ __nv_bfloat16 g_wvh[3*DMODEL*DMODEL], g_wvl[3*DMODEL*DMODEL];
__device__ __nv_bfloat16 g_w1h[3*DHID*DMODEL],   g_w1l[3*DHID*DMODEL];
__device__ __nv_bfloat16 g_w2h[3*DMODEL*DHID],   g_w2l[3*DMODEL*DHID];
__device__ __nv_bfloat16 g_fmh[MTOT*DMODEL], g_fml[MTOT*DMODEL];
__device__ __nv_bfloat16 g_fsh[MTOT*DMODEL], g_fsl[MTOT*DMODEL];
__device__ __nv_bfloat16 g_fqh[MTOT*DMODEL], g_fql[MTOT*DMODEL];
__device__ __nv_bfloat16 g_cssh[MTOT*DMODEL], g_cssl[MTOT*DMODEL];
__device__ __nv_bfloat16 g_cqqh[MTOT*DMODEL], g_cqql[MTOT*DMODEL];
__device__ __nv_bfloat16 g_xh[MTOT*DMODEL],  g_xl[MTOT*DMODEL];
__device__ __nv_bfloat16 g_hh[MTOT*DHID],    g_hl[MTOT*DHID];

// ---------------------------------------------------------------------------
// helpers
// ---------------------------------------------------------------------------
__device__ __forceinline__ uint32_t sptr(const void* p) {
    return (uint32_t)__cvta_generic_to_shared(p);
}
__device__ __forceinline__ void ldm4(uint32_t a, uint32_t& r0, uint32_t& r1,
                                     uint32_t& r2, uint32_t& r3) {
    asm volatile("ldmatrix.sync.aligned.m8n8.x4.shared.b16 {%0,%1,%2,%3},[%4];"
                 : "=r"(r0), "=r"(r1), "=r"(r2), "=r"(r3) : "r"(a));
}
__device__ __forceinline__ void mma_bf16(float c[4], const uint32_t a[4],
                                         const uint32_t b[2]) {
    asm volatile(
        "mma.sync.aligned.m16n8k16.row.col.f32.bf16.bf16.f32 "
        "{%0,%1,%2,%3},{%4,%5,%6,%7},{%8,%9},{%0,%1,%2,%3};"
        : "+f"(c[0]), "+f"(c[1]), "+f"(c[2]), "+f"(c[3])
        : "r"(a[0]), "r"(a[1]), "r"(a[2]), "r"(a[3]), "r"(b[0]), "r"(b[1]));
}
__device__ __forceinline__ float e2(float x) {
    float y; asm("ex2.approx.ftz.f32 %0,%1;" : "=f"(y) : "f"(x)); return y;
}
__device__ __forceinline__ uint32_t packbf(float a, float b) {
    const __nv_bfloat162 t = __float22bfloat162_rn(make_float2(a, b));
    return *reinterpret_cast<const uint32_t*>(&t);
}
__device__ __forceinline__ void split2(float v, __nv_bfloat16& h, __nv_bfloat16& l) {
    h = __float2bfloat16(v);
    l = __float2bfloat16(v - __bfloat162float(h));
}
__device__ __forceinline__ void cpa16(uint32_t s, const void* g) {
    asm volatile("cp.async.cg.shared.global [%0],[%1],16;" :: "r"(s), "l"(g));
}
__device__ __forceinline__ void cpa_commit() {
    asm volatile("cp.async.commit_group;");
}
template <int N>
__device__ __forceinline__ void cpa_wait() {
    asm volatile("cp.async.wait_group %0;" :: "n"(N));
}

// ---------------------------------------------------------------------------
// fused input split: {Fm, Fs, Fq} fp32 -> bf16 (hi, lo)
// ---------------------------------------------------------------------------
#define SEG4 (MTOT * DMODEL / 4)

__global__ __launch_bounds__(256)
void split_in_kernel(const float* __restrict__ Fm, const float* __restrict__ Fs,
                     const float* __restrict__ Fq)
{
    const int i = blockIdx.x * 256 + threadIdx.x;
    if (i >= 3 * SEG4) return;
    const int seg = i / SEG4;
    const int off = i - seg * SEG4;
    const float* src = (seg == 0) ? Fm : (seg == 1) ? Fs : Fq;
    __nv_bfloat16* dh = (seg == 0) ? g_fmh : (seg == 1) ? g_fsh : g_fqh;
    __nv_bfloat16* dl = (seg == 0) ? g_fml : (seg == 1) ? g_fsl : g_fql;
    const float4 v = *(const float4*)(src + (size_t)off * 4);
    __nv_bfloat16 h0, h1, h2, h3, l0, l1, l2, l3;
    split2(v.x, h0, l0); split2(v.y, h1, l1);
    split2(v.z, h2, l2); split2(v.w, h3, l3);
    *(__nv_bfloat162*)(dh + (size_t)off * 4)     = __nv_bfloat162(h0, h1);
    *(__nv_bfloat162*)(dh + (size_t)off * 4 + 2) = __nv_bfloat162(h2, h3);
    *(__nv_bfloat162*)(dl + (size_t)off * 4)     = __nv_bfloat162(l0, l1);
    *(__nv_bfloat162*)(dl + (size_t)off * 4 + 2) = __nv_bfloat162(l2, l3);
}

// ---------------------------------------------------------------------------
// fused weight split: {Wq(scaled by QSC), Wk, Wv, w1, w2} fp32 -> bf16 (hi,lo)
// ---------------------------------------------------------------------------
#define WQ4 (3 * DMODEL * DMODEL / 4)     // 196608
#define W14 (3 * DHID * DMODEL / 4)       // 786432
#define WTOT4 (3 * WQ4 + 2 * W14)

__global__ __launch_bounds__(256)
void split_w_kernel(const float* __restrict__ Wq, const float* __restrict__ Wk,
                    const float* __restrict__ Wv, const float* __restrict__ w1,
                    const float* __restrict__ w2)
{
    const int i = blockIdx.x * 256 + threadIdx.x;
    if (i >= WTOT4) return;
    const float* src; __nv_bfloat16 *dh, *dl; int off; float sc = 1.f;
    if (i < WQ4)                 { src = Wq; dh = g_wqh; dl = g_wql; off = i; sc = QSC; }
    else if (i < 2 * WQ4)        { src = Wk; dh = g_wkh; dl = g_wkl; off = i - WQ4; }
    else if (i < 3 * WQ4)        { src = Wv; dh = g_wvh; dl = g_wvl; off = i - 2 * WQ4; }
    else if (i < 3 * WQ4 + W14)  { src = w1; dh = g_w1h; dl = g_w1l; off = i - 3 * WQ4; }
    else                         { src = w2; dh = g_w2h; dl = g_w2l; off = i - 3 * WQ4 - W14; }
    float4 v = *(const float4*)(src + (size_t)off * 4);
    v.x *= sc; v.y *= sc; v.z *= sc; v.w *= sc;
    __nv_bfloat16 h0, h1, h2, h3, l0, l1, l2, l3;
    split2(v.x, h0, l0); split2(v.y, h1, l1);
    split2(v.z, h2, l2); split2(v.w, h3, l3);
    *(__nv_bfloat162*)(dh + (size_t)off * 4)     = __nv_bfloat162(h0, h1);
    *(__nv_bfloat162*)(dh + (size_t)off * 4 + 2) = __nv_bfloat162(h2, h3);
    *(__nv_bfloat162*)(dl + (size_t)off * 4)     = __nv_bfloat162(l0, l1);
    *(__nv_bfloat162*)(dl + (size_t)off * 4 + 2) = __nv_bfloat162(l2, l3);
}

// ---------------------------------------------------------------------------
// bf16 3-pass split GEMM body (validated R10 inner loop):
//   C = epi( (Ah+Al)[M,K] @ (Bh+Bl)[N,K]^T )
// 128x128x32 CTA tile, 4 warps (64x64 each), cp.async double-buffered.
// OUT: 0 -> fp32 C;  1 -> relu + bf16 split (Ch, Cl);  2 -> bf16 (Ch only)
// ---------------------------------------------------------------------------
#define TBM 128
#define TBN 128
#define TBK 32
#define TAS 40
#define REGB  (TBM * TAS * 2)      // 10240
#define BUFSZ (4 * REGB)           // Ah | Al | Bh | Bl = 40960
#define GEMM_SMEM (2 * BUFSZ)      // 81920 -> 2 CTAs/SM

extern __shared__ char gsm[];

template <int OUT>
__device__ __forceinline__
void gemm_body(const __nv_bfloat16* __restrict__ Agh, const __nv_bfloat16* __restrict__ Agl,
               const __nv_bfloat16* __restrict__ Bgh, const __nv_bfloat16* __restrict__ Bgl,
               float* __restrict__ C, __nv_bfloat16* __restrict__ Ch,
               __nv_bfloat16* __restrict__ Cl, int M, int N, int K)
{
    const int tid  = threadIdx.x;
    const int lane = tid & 31;
    const int wid  = tid >> 5;
    const int wm   = wid & 1;        // 2 m-warps * 64 rows
    const int wn   = wid >> 1;       // 2 n-warps * 64 cols
    const int bm   = blockIdx.y * TBM;
    const int bn   = blockIdx.x * TBN;

    const uint32_t sbase = sptr(gsm);

    auto load_tile = [&](int buf, int k0) {
        const uint32_t b = sbase + buf * BUFSZ;
#pragma unroll
        for (int j = 0; j < 4; ++j) {
            const int c = tid + j * 128;
            const int row = c >> 2, kc = (c & 3) << 3;
            const uint32_t so = (uint32_t)(row * TAS + kc) * 2;
            const size_t goA = (size_t)(bm + row) * K + k0 + kc;
            const size_t goB = (size_t)(bn + row) * K + k0 + kc;
            cpa16(b + so,            Agh + goA);
            cpa16(b + REGB + so,     Agl + goA);
            cpa16(b + 2 * REGB + so, Bgh + goB);
            cpa16(b + 3 * REGB + so, Bgl + goB);
        }
        cpa_commit();
    };

    float c[4][8][4];
#pragma unroll
    for (int mi = 0; mi < 4; ++mi)
#pragma unroll
        for (int ni = 0; ni < 8; ++ni)
#pragma unroll
            for (int e = 0; e < 4; ++e) c[mi][ni][e] = 0.f;

    const int lmA = lane & 15;
    const int lkA = (lane >> 4) << 3;
    const int lnB = ((lane >> 4) & 1) * 8 + (lane & 7);
    const int lkB = ((lane >> 3) & 1) * 8;
    const uint32_t relA = (uint32_t)((wm * 64 + lmA) * TAS + lkA) * 2;
    const uint32_t relB = (uint32_t)((wn * 64 + lnB) * TAS + lkB) * 2;

    const int niter = K / TBK;
    load_tile(0, 0);

    for (int it = 0; it < niter; ++it) {
        const int cur = it & 1;
        if (it + 1 < niter) { load_tile(cur ^ 1, (it + 1) * TBK); cpa_wait<1>(); }
        else cpa_wait<0>();
        __syncthreads();

        const uint32_t b = sbase + cur * BUFSZ;
        const uint32_t aAh = b + relA,            aAl = b + REGB + relA;
        const uint32_t aBh = b + 2 * REGB + relB, aBl = b + 3 * REGB + relB;

#pragma unroll
        for (int ks = 0; ks < 2; ++ks) {
            const uint32_t ko = ks * 32;
            uint32_t bhf[8][2], blf[8][2];
#pragma unroll
            for (int p = 0; p < 4; ++p) {
                ldm4(aBh + p * (16 * TAS * 2) + ko,
                     bhf[2*p][0], bhf[2*p][1], bhf[2*p+1][0], bhf[2*p+1][1]);
                ldm4(aBl + p * (16 * TAS * 2) + ko,
                     blf[2*p][0], blf[2*p][1], blf[2*p+1][0], blf[2*p+1][1]);
            }
#pragma unroll
            for (int mi = 0; mi < 4; ++mi) {
                uint32_t ah[4], al[4];
                ldm4(aAh + mi * (16 * TAS * 2) + ko, ah[0], ah[1], ah[2], ah[3]);
                ldm4(aAl + mi * (16 * TAS * 2) + ko, al[0], al[1], al[2], al[3]);
#pragma unroll
                for (int ni = 0; ni < 8; ++ni) mma_bf16(c[mi][ni], ah, bhf[ni]);
#pragma unroll
                for (int ni = 0; ni < 8; ++ni) mma_bf16(c[mi][ni], ah, blf[ni]);
#pragma unroll
                for (int ni = 0; ni < 8; ++ni) mma_bf16(c[mi][ni], al, bhf[ni]);
            }
        }
        __syncthreads();
    }

#pragma unroll
    for (int mi = 0; mi < 4; ++mi) {
        const int row0 = bm + wm * 64 + mi * 16 + (lane >> 2);
#pragma unroll
        for (int ni = 0; ni < 8; ++ni) {
            const int col = bn + wn * 64 + ni * 8 + ((lane & 3) << 1);
            float v0 = c[mi][ni][0], v1 = c[mi][ni][1];
            float v2 = c[mi][ni][2], v3 = c[mi][ni][3];
            if (OUT == 0) {
                float2 a; a.x = v0; a.y = v1;
                float2 bq; bq.x = v2; bq.y = v3;
                *(float2*)&C[(size_t)row0 * N + col]       = a;
                *(float2*)&C[(size_t)(row0 + 8) * N + col] = bq;
            } else if (OUT == 1) {
                v0 = fmaxf(v0, 0.f); v1 = fmaxf(v1, 0.f);
                v2 = fmaxf(v2, 0.f); v3 = fmaxf(v3, 0.f);
                __nv_bfloat16 h0, h1, h2, h3, l0, l1, l2, l3;
                split2(v0, h0, l0); split2(v1, h1, l1);
                split2(v2, h2, l2); split2(v3, h3, l3);
                *(__nv_bfloat162*)&Ch[(size_t)row0 * N + col]       = __nv_bfloat162(h0, h1);
                *(__nv_bfloat162*)&Cl[(size_t)row0 * N + col]       = __nv_bfloat162(l0, l1);
                *(__nv_bfloat162*)&Ch[(size_t)(row0 + 8) * N + col] = __nv_bfloat162(h2, h3);
                *(__nv_bfloat162*)&Cl[(size_t)(row0 + 8) * N + col] = __nv_bfloat162(l2, l3);
            } else {
                *(__nv_bfloat162*)&Ch[(size_t)row0 * N + col] =
                    __nv_bfloat162(__float2bfloat16(v0), __float2bfloat16(v1));
                *(__nv_bfloat162*)&Ch[(size_t)(row0 + 8) * N + col] =
                    __nv_bfloat162(__float2bfloat16(v2), __float2bfloat16(v3));
            }
        }
    }
}

template <int OUT>
__global__ __launch_bounds__(128, 2)
void gemm_bf(const __nv_bfloat16* __restrict__ Agh, const __nv_bfloat16* __restrict__ Agl,
             const __nv_bfloat16* __restrict__ Bgh, const __nv_bfloat16* __restrict__ Bgl,
             float* __restrict__ C, __nv_bfloat16* __restrict__ Ch,
             __nv_bfloat16* __restrict__ Cl, int M, int N, int K)
{
    gemm_body<OUT>(Agh, Agl, Bgh, Bgl, C, Ch, Cl, M, N, K);
}

// fused QKV projection: grid.z selects {Q, K, V}; bf16 output
__global__ __launch_bounds__(128, 2)
void gemm_qkv(const __nv_bfloat16* __restrict__ A0h, const __nv_bfloat16* __restrict__ A0l,
              const __nv_bfloat16* __restrict__ A1h, const __nv_bfloat16* __restrict__ A1l,
              const __nv_bfloat16* __restrict__ A2h, const __nv_bfloat16* __restrict__ A2l,
              const __nv_bfloat16* __restrict__ W0h, const __nv_bfloat16* __restrict__ W0l,
              const __nv_bfloat16* __restrict__ W1h, const __nv_bfloat16* __restrict__ W1l,
              const __nv_bfloat16* __restrict__ W2h, const __nv_bfloat16* __restrict__ W2l,
              __nv_bfloat16* __restrict__ Cq, __nv_bfloat16* __restrict__ Ck,
              __nv_bfloat16* __restrict__ Cv)
{
    const __nv_bfloat16 *Ah, *Al, *Bh, *Bl;
    __nv_bfloat16* Co;
    if (blockIdx.z == 0)      { Ah = A0h; Al = A0l; Bh = W0h; Bl = W0l; Co = Cq; }
    else if (blockIdx.z == 1) { Ah = A1h; Al = A1l; Bh = W1h; Bl = W1l; Co = Ck; }
    else                      { Ah = A2h; Al = A2l; Bh = W2h; Bl = W2l; Co = Cv; }
    gemm_body<2>(Ah, Al, Bh, Bl, nullptr, Co, nullptr, MTOT, DMODEL, DMODEL);
}

// ---------------------------------------------------------------------------
// Tensor-core flash attention — bf16 inputs (pre-scaled Q), validated core
// ---------------------------------------------------------------------------
#define FM  64
#define FN  64
#define FQS 264
#define VTS 72
#define FA_SMEM_BYTES ((FM*FQS + FN*FQS + GSZ*VTS) * 2)

extern __shared__ char fa_raw[];

__global__ __launch_bounds__(128, 2)
void flash_tc(const __nv_bfloat16* __restrict__ Q, const __nv_bfloat16* __restrict__ K,
              const __nv_bfloat16* __restrict__ V, float* __restrict__ O)
{
    __nv_bfloat16* Qs = (__nv_bfloat16*)fa_raw;
    __nv_bfloat16* Ks = Qs + FM * FQS;
    __nv_bfloat16* Vt = Ks + FN * FQS;

    const int tid  = threadIdx.x;
    const int lane = tid & 31;
    const int w    = tid >> 5;
    const int qbase = blockIdx.x * FM;
    const int h = blockIdx.y, b = blockIdx.z;
    const size_t bstride = (size_t)SEQ * DMODEL;
    const __nv_bfloat16* Qb = Q + b * bstride + h * GSZ;
    const __nv_bfloat16* Kb = K + b * bstride + h * GSZ;
    const __nv_bfloat16* Vb = V + b * bstride + h * GSZ;

    const int lmA = lane & 15;
    const int lkA = (lane >> 4) << 3;
    const int lnB = ((lane >> 4) & 1) * 8 + (lane & 7);
    const int lkB = ((lane >> 3) & 1) * 8;

    const uint32_t aQ = sptr(Qs) + (uint32_t)((w * 16 + lmA) * FQS + lkA) * 2;
    const uint32_t aK = sptr(Ks) + (uint32_t)(lnB * FQS + lkB) * 2;
    const uint32_t aV = sptr(Vt) + (uint32_t)(lnB * VTS + lkB) * 2;

    // stage Q: straight bf16 copy (scale pre-folded into Wq)
#pragma unroll
    for (int j = 0; j < 16; ++j) {
        const int idx = tid + j * 128;          // 64 rows x 32 chunks of 8 bf16
        const int row = idx >> 5, c8 = idx & 31;
        const uint4 u = *(const uint4*)(Qb + (size_t)(qbase + row) * DMODEL + c8 * 8);
        *(uint4*)(Qs + row * FQS + c8 * 8) = u;
    }

    float mA = -1e30f, mB = -1e30f, lA = 0.f, lB = 0.f;
    float o[32][4];
#pragma unroll
    for (int f = 0; f < 32; ++f)
#pragma unroll
        for (int e = 0; e < 4; ++e) o[f][e] = 0.f;

    const int vkcol = tid & 63;
    const int vdch  = tid >> 6;

    for (int kb = 0; kb < SEQ; kb += FN) {
        __syncthreads();
        // stage K: straight bf16 copy
#pragma unroll
        for (int j = 0; j < 16; ++j) {
            const int idx = tid + j * 128;
            const int row = idx >> 5, c8 = idx & 31;
            const uint4 u = *(const uint4*)(Kb + (size_t)(kb + row) * DMODEL + c8 * 8);
            *(uint4*)(Ks + row * FQS + c8 * 8) = u;
        }
        // stage V transposed (bf16 source)
        {
            const __nv_bfloat16* vsrc = Vb + (size_t)(kb + vkcol) * DMODEL + vdch * 128;
#pragma unroll
            for (int j = 0; j < 16; ++j) {
                union { uint4 u; __nv_bfloat16 e[8]; } wv;
                wv.u = *(const uint4*)(vsrc + j * 8);
                const int d = vdch * 128 + j * 8;
#pragma unroll
                for (int i = 0; i < 8; ++i)
                    Vt[(d + i) * VTS + vkcol] = wv.e[i];
            }
        }
        __syncthreads();

        float s[8][4];
#pragma unroll
        for (int f = 0; f < 8; ++f)
#pragma unroll
            for (int e = 0; e < 4; ++e) s[f][e] = 0.f;

#pragma unroll
        for (int ks = 0; ks < 16; ++ks) {
            uint32_t af[4];
            ldm4(aQ + ks * 32, af[0], af[1], af[2], af[3]);
#pragma unroll
            for (int g = 0; g < 4; ++g) {
                uint32_t b0[2], b1[2];
                ldm4(aK + (uint32_t)(g * 16 * FQS) * 2 + ks * 32,
                     b0[0], b0[1], b1[0], b1[1]);
                mma_bf16(s[2 * g],     af, b0);
                mma_bf16(s[2 * g + 1], af, b1);
            }
        }

        float mxA = -1e30f, mxB = -1e30f;
#pragma unroll
        for (int f = 0; f < 8; ++f) {
            mxA = fmaxf(mxA, fmaxf(s[f][0], s[f][1]));
            mxB = fmaxf(mxB, fmaxf(s[f][2], s[f][3]));
        }
        mxA = fmaxf(mxA, __shfl_xor_sync(0xffffffffu, mxA, 1));
        mxA = fmaxf(mxA, __shfl_xor_sync(0xffffffffu, mxA, 2));
        mxB = fmaxf(mxB, __shfl_xor_sync(0xffffffffu, mxB, 1));
        mxB = fmaxf(mxB, __shfl_xor_sync(0xffffffffu, mxB, 2));
        const float mnA = fmaxf(mA, mxA);
        const float mnB = fmaxf(mB, mxB);
        float sumA = 0.f, sumB = 0.f;
#pragma unroll
        for (int f = 0; f < 8; ++f) {
            s[f][0] = e2(s[f][0] - mnA); s[f][1] = e2(s[f][1] - mnA);
            s[f][2] = e2(s[f][2] - mnB); s[f][3] = e2(s[f][3] - mnB);
            sumA += s[f][0] + s[f][1];
            sumB += s[f][2] + s[f][3];
        }
        sumA += __shfl_xor_sync(0xffffffffu, sumA, 1);
        sumA += __shfl_xor_sync(0xffffffffu, sumA, 2);
        sumB += __shfl_xor_sync(0xffffffffu, sumB, 1);
        sumB += __shfl_xor_sync(0xffffffffu, sumB, 2);
        const float ccA = e2(mA - mnA);
        const float ccB = e2(mB - mnB);
        lA = lA * ccA + sumA; mA = mnA;
        lB = lB * ccB + sumB; mB = mnB;

#pragma unroll
        for (int f = 0; f < 32; ++f) {
            o[f][0] *= ccA; o[f][1] *= ccA;
            o[f][2] *= ccB; o[f][3] *= ccB;
        }

#pragma unroll
        for (int kf = 0; kf < 4; ++kf) {
            uint32_t ap[4];
            ap[0] = packbf(s[2 * kf][0],     s[2 * kf][1]);
            ap[1] = packbf(s[2 * kf][2],     s[2 * kf][3]);
            ap[2] = packbf(s[2 * kf + 1][0], s[2 * kf + 1][1]);
            ap[3] = packbf(s[2 * kf + 1][2], s[2 * kf + 1][3]);
#pragma unroll
            for (int g = 0; g < 16; ++g) {
                uint32_t b0[2], b1[2];
                ldm4(aV + (uint32_t)(g * 16 * VTS) * 2 + kf * 32,
                     b0[0], b0[1], b1[0], b1[1]);
                mma_bf16(o[2 * g],     ap, b0);
                mma_bf16(o[2 * g + 1], ap, b1);
            }
        }
    }

    const float liA = 1.f / lA;
    const float liB = 1.f / lB;
    const int rowA = qbase + w * 16 + (lane >> 2);
    float* Ob = O + b * bstride + h * GSZ;
#pragma unroll
    for (int f = 0; f < 32; ++f) {
        const int col = f * 8 + ((lane & 3) << 1);
        float2 rA; rA.x = o[f][0] * liA; rA.y = o[f][1] * liA;
        float2 rB; rB.x = o[f][2] * liB; rB.y = o[f][3] * liB;
        *(float2*)&Ob[(size_t)rowA * DMODEL + col]       = rA;
        *(float2*)&Ob[(size_t)(rowA + 8) * DMODEL + col] = rB;
    }
}

// ---------------------------------------------------------------------------
// out = LayerNorm(X + R); optionally emit bf16 (hi, lo) split
// ---------------------------------------------------------------------------
__global__ __launch_bounds__(128)
void add_ln_kernel(const float* __restrict__ X, const float* __restrict__ R,
                   const float* __restrict__ g, const float* __restrict__ bt,
                   float eps, float* __restrict__ out,
                   __nv_bfloat16* __restrict__ oh, __nv_bfloat16* __restrict__ ol,
                   int doSplit)
{
    const int row = blockIdx.x;
    const int tid = threadIdx.x;
    float4 v = *(const float4*)(X + (size_t)row * DMODEL + tid * 4);
    const float4 rr = *(const float4*)(R + (size_t)row * DMODEL + tid * 4);
    v.x += rr.x; v.y += rr.y; v.z += rr.z; v.w += rr.w;
    float s  = v.x + v.y + v.z + v.w;
    float sq = v.x * v.x + v.y * v.y + v.z * v.z + v.w * v.w;
#pragma unroll
    for (int off = 16; off; off >>= 1) {
        s  += __shfl_xor_sync(0xffffffffu, s,  off);
        sq += __shfl_xor_sync(0xffffffffu, sq, off);
    }
    __shared__ float ssum[4], ssq[4];
    const int w = tid >> 5, l = tid & 31;
    if (l == 0) { ssum[w] = s; ssq[w] = sq; }
    __syncthreads();
    s  = ssum[0] + ssum[1] + ssum[2] + ssum[3];
    sq = ssq[0]  + ssq[1]  + ssq[2]  + ssq[3];
    const float mean = s * (1.f / DMODEL);
    const float var  = sq * (1.f / DMODEL) - mean * mean;
    const float rstd = rsqrtf(var + eps);
    const float4 gg = *(const float4*)(g  + tid * 4);
    const float4 bb = *(const float4*)(bt + tid * 4);
    float4 r;
    r.x = (v.x - mean) * rstd * gg.x + bb.x;
    r.y = (v.y - mean) * rstd * gg.y + bb.y;
    r.z = (v.z - mean) * rstd * gg.z + bb.z;
    r.w = (v.w - mean) * rstd * gg.w + bb.w;
    *(float4*)(out + (size_t)row * DMODEL + tid * 4) = r;
    if (doSplit) {
        __nv_bfloat16 h0, h1, h2, h3, l0, l1, l2, l3;
        split2(r.x, h0, l0); split2(r.y, h1, l1);
        split2(r.z, h2, l2); split2(r.w, h3, l3);
        const size_t o = (size_t)row * DMODEL + tid * 4;
        *(__nv_bfloat162*)(oh + o)     = __nv_bfloat162(h0, h1);
        *(__nv_bfloat162*)(oh + o + 2) = __nv_bfloat162(h2, h3);
        *(__nv_bfloat162*)(ol + o)     = __nv_bfloat162(l0, l1);
        *(__nv_bfloat162*)(ol + o + 2) = __nv_bfloat162(l2, l3);
    }
}

// ---------------------------------------------------------------------------
// host side
// ---------------------------------------------------------------------------
extern "C" void kernel_launch(void* const* d_in, const int* in_sizes, int n_in,
                              void* d_out, int out_size)
{
    (void)in_sizes; (void)n_in; (void)out_size;
    const float* Fm   = (const float*)d_in[0];
    const float* Fs   = (const float*)d_in[1];
    const float* Fq   = (const float*)d_in[2];
    const float* Wq   = (const float*)d_in[3];
    const float* Wk   = (const float*)d_in[4];
    const float* Wv   = (const float*)d_in[5];
    const float* lng  = (const float*)d_in[6];
    const float* lnb  = (const float*)d_in[7];
    const float* w1   = (const float*)d_in[8];
    const float* w2   = (const float*)d_in[9];
    const float* flg  = (const float*)d_in[10];
    const float* flb  = (const float*)d_in[11];
    float* out = (float*)d_out;

    float *att, *x, *y, *css, *cqq;
    cudaGetSymbolAddress((void**)&att, g_att);
    cudaGetSymbolAddress((void**)&x,   g_x);
    cudaGetSymbolAddress((void**)&y,   g_y);
    cudaGetSymbolAddress((void**)&css, g_css);
    cudaGetSymbolAddress((void**)&cqq, g_cqq);

    __nv_bfloat16 *qb, *kb, *vb;
    __nv_bfloat16 *wqh, *wql, *wkh, *wkl, *wvh, *wvl, *w1h, *w1l, *w2h, *w2l;
    __nv_bfloat16 *fmh, *fml, *fsh, *fsl, *fqh, *fql;
    __nv_bfloat16 *cssh, *cssl, *cqqh, *cqql, *xh, *xl, *hh, *hl;
    cudaGetSymbolAddress((void**)&qb, g_qb);
    cudaGetSymbolAddress((void**)&kb, g_kb);
    cudaGetSymbolAddress((void**)&vb, g_vb);
    cudaGetSymbolAddress((void**)&wqh, g_wqh); cudaGetSymbolAddress((void**)&wql, g_wql);
    cudaGetSymbolAddress((void**)&wkh, g_wkh); cudaGetSymbolAddress((void**)&wkl, g_wkl);
    cudaGetSymbolAddress((void**)&wvh, g_wvh); cudaGetSymbolAddress((void**)&wvl, g_wvl);
    cudaGetSymbolAddress((void**)&w1h, g_w1h); cudaGetSymbolAddress((void**)&w1l, g_w1l);
    cudaGetSymbolAddress((void**)&w2h, g_w2h); cudaGetSymbolAddress((void**)&w2l, g_w2l);
    cudaGetSymbolAddress((void**)&fmh, g_fmh); cudaGetSymbolAddress((void**)&fml, g_fml);
    cudaGetSymbolAddress((void**)&fsh, g_fsh); cudaGetSymbolAddress((void**)&fsl, g_fsl);
    cudaGetSymbolAddress((void**)&fqh, g_fqh); cudaGetSymbolAddress((void**)&fql, g_fql);
    cudaGetSymbolAddress((void**)&cssh, g_cssh); cudaGetSymbolAddress((void**)&cssl, g_cssl);
    cudaGetSymbolAddress((void**)&cqqh, g_cqqh); cudaGetSymbolAddress((void**)&cqql, g_cqql);
    cudaGetSymbolAddress((void**)&xh, g_xh);   cudaGetSymbolAddress((void**)&xl, g_xl);
    cudaGetSymbolAddress((void**)&hh, g_hh);   cudaGetSymbolAddress((void**)&hl, g_hl);

    cudaFuncSetAttribute(flash_tc, cudaFuncAttributeMaxDynamicSharedMemorySize,
                         FA_SMEM_BYTES);
    cudaFuncSetAttribute(gemm_bf<0>, cudaFuncAttributeMaxDynamicSharedMemorySize,
                         GEMM_SMEM);
    cudaFuncSetAttribute(gemm_bf<1>, cudaFuncAttributeMaxDynamicSharedMemorySize,
                         GEMM_SMEM);
    cudaFuncSetAttribute(gemm_qkv, cudaFuncAttributeMaxDynamicSharedMemorySize,
                         GEMM_SMEM);

    // fused preprocessing (2 launches); Wq pre-scaled by QSC
    split_in_kernel<<<(3 * SEG4 + 255) / 256, 256>>>(Fm, Fs, Fq);
    split_w_kernel<<<(WTOT4 + 255) / 256, 256>>>(Wq, Wk, Wv, w1, w2);

    const dim3 gqkv(DMODEL / TBN, MTOT / TBM, 3);   // (4, 64, 3)
    const dim3 gp(DMODEL / TBN, MTOT / TBM);        // (4, 64)
    const dim3 gh(DHID / TBN,   MTOT / TBM);        // (16, 64)
    const dim3 ga(SEQ / FM, NHEADS, BATCH);

    auto run_block = [&](int i,
                         const __nv_bfloat16* Qh, const __nv_bfloat16* Ql,
                         const __nv_bfloat16* Kh, const __nv_bfloat16* Kl,
                         const __nv_bfloat16* Vh, const __nv_bfloat16* Vl,
                         const float* Rp, float* op,
                         __nv_bfloat16* oph, __nv_bfloat16* opl, int splitOut) {
        const size_t wOff  = (size_t)i * DMODEL * DMODEL;
        const size_t w1Off = (size_t)i * DHID * DMODEL;
        gemm_qkv<<<gqkv, 128, GEMM_SMEM>>>(Qh, Ql, Kh, Kl, Vh, Vl,
                                           wqh + wOff, wql + wOff,
                                           wkh + wOff, wkl + wOff,
                                           wvh + wOff, wvl + wOff,
                                           qb, kb, vb);
        flash_tc<<<ga, 128, FA_SMEM_BYTES>>>(qb, kb, vb, att);
        add_ln_kernel<<<MTOT, 128>>>(att, Rp, lng + i * DMODEL, lnb + i * DMODEL,
                                     1e-5f, x, xh, xl, 1);
        gemm_bf<1><<<gh, 128, GEMM_SMEM>>>(xh, xl, w1h + w1Off, w1l + w1Off,
                                           nullptr, hh, hl, MTOT, DHID, DMODEL);
        gemm_bf<0><<<gp, 128, GEMM_SMEM>>>(hh, hl, w2h + w1Off, w2l + w1Off,
                                           y, nullptr, nullptr, MTOT, DMODEL, DHID);
        add_ln_kernel<<<MTOT, 128>>>(y, x, flg + i * DMODEL, flb + i * DMODEL,
                                     1e-6f, op, oph, opl, splitOut);
    };

    // css = blk(0, Fs, Fs, Fm, Fm); cqq = blk(1, Fq, Fq, Fq, Fq);
    // csq = blk(2, cqq, Fs, css, css)
    run_block(0, fsh, fsl, fsh, fsl, fmh, fml, Fm, css, cssh, cssl, 1);
    run_block(1, fqh, fql, fqh, fql, fqh, fql, Fq, cqq, cqqh, cqql, 1);
    run_block(2, cqqh, cqql, fsh, fsl, cssh, cssl, css, out, nullptr, nullptr, 0);
}

// round 14
// speedup vs baseline: 1.7090x; 1.0762x over previous
#include <cuda_runtime.h>
#include <cuda_bf16.h>
#include <cstdint>

// ---------------------------------------------------------------------------
// Problem constants
// ---------------------------------------------------------------------------
#define BATCH   4
#define SEQ     2048
#define DMODEL  512
#define DHID    2048
#define NHEADS  2
#define GSZ     256
#define MTOT    (BATCH * SEQ)       // 8192

// softmax scale folded into Wq: 1/sqrt(256) * log2(e)
#define QSC 0.09016994374947424f

// ---------------------------------------------------------------------------
// Scratch (device globals)
// ---------------------------------------------------------------------------
__device__ __nv_bfloat16 g_qb[MTOT * DMODEL];
__device__ __nv_bfloat16 g_kb[MTOT * DMODEL];
__device__ __nv_bfloat16 g_vb[MTOT * DMODEL];
__device__ float g_att[MTOT * DMODEL];
__device__ float g_x  [MTOT * DMODEL];
__device__ float g_y  [MTOT * DMODEL];
__device__ float g_css[MTOT * DMODEL];
__device__ float g_cqq[MTOT * DMODEL];

__device__ __nv_bfloat16 g_wqh[3*DMODEL*DMODEL], g_wql[3*DMODEL*DMODEL];
__device__ __nv_bfloat16 g_wkh[3*DMODEL*DMODEL], g_wkl[3*DMODEL*DMODEL];
__device__ __nv_bfloat16 g_wvh[3*DMODEL*DMODEL], g_wvl[3*DMODEL*DMODEL];
__device__ __nv_bfloat16 g_w1h[3*DHID*DMODEL],   g_w1l[3*DHID*DMODEL];
__device__ __nv_bfloat16 g_w2h[3*DMODEL*DHID],   g_w2l[3*DMODEL*DHID];
__device__ __nv_bfloat16 g_fmh[MTOT*DMODEL], g_fml[MTOT*DMODEL];
__device__ __nv_bfloat16 g_fsh[MTOT*DMODEL], g_fsl[MTOT*DMODEL];
__device__ __nv_bfloat16 g_fqh[MTOT*DMODEL], g_fql[MTOT*DMODEL];
__device__ __nv_bfloat16 g_cssh[MTOT*DMODEL], g_cssl[MTOT*DMODEL];
__device__ __nv_bfloat16 g_cqqh[MTOT*DMODEL], g_cqql[MTOT*DMODEL];
__device__ __nv_bfloat16 g_xh[MTOT*DMODEL],  g_xl[MTOT*DMODEL];
__device__ __nv_bfloat16 g_hh[MTOT*DHID],    g_hl[MTOT*DHID];

// ---------------------------------------------------------------------------
// helpers
// ---------------------------------------------------------------------------
__device__ __forceinline__ uint32_t sptr(const void* p) {
    return (uint32_t)__cvta_generic_to_shared(p);
}
__device__ __forceinline__ void ldm4(uint32_t a, uint32_t& r0, uint32_t& r1,
                                     uint32_t& r2, uint32_t& r3) {
    asm volatile("ldmatrix.sync.aligned.m8n8.x4.shared.b16 {%0,%1,%2,%3},[%4];"
                 : "=r"(r0), "=r"(r1), "=r"(r2), "=r"(r3) : "r"(a));
}
__device__ __forceinline__ void ldm4t(uint32_t a, uint32_t& r0, uint32_t& r1,
                                      uint32_t& r2, uint32_t& r3) {
    asm volatile("ldmatrix.sync.aligned.m8n8.x4.trans.shared.b16 {%0,%1,%2,%3},[%4];"
                 : "=r"(r0), "=r"(r1), "=r"(r2), "=r"(r3) : "r"(a));
}
__device__ __forceinline__ void mma_bf16(float c[4], const uint32_t a[4],
                                         const uint32_t b[2]) {
    asm volatile(
        "mma.sync.aligned.m16n8k16.row.col.f32.bf16.bf16.f32 "
        "{%0,%1,%2,%3},{%4,%5,%6,%7},{%8,%9},{%0,%1,%2,%3};"
        : "+f"(c[0]), "+f"(c[1]), "+f"(c[2]), "+f"(c[3])
        : "r"(a[0]), "r"(a[1]), "r"(a[2]), "r"(a[3]), "r"(b[0]), "r"(b[1]));
}
__device__ __forceinline__ float e2(float x) {
    float y; asm("ex2.approx.ftz.f32 %0,%1;" : "=f"(y) : "f"(x)); return y;
}
__device__ __forceinline__ uint32_t packbf(float a, float b) {
    const __nv_bfloat162 t = __float22bfloat162_rn(make_float2(a, b));
    return *reinterpret_cast<const uint32_t*>(&t);
}
__device__ __forceinline__ void split2(float v, __nv_bfloat16& h, __nv_bfloat16& l) {
    h = __float2bfloat16(v);
    l = __float2bfloat16(v - __bfloat162float(h));
}
__device__ __forceinline__ void cpa16(uint32_t s, const void* g) {
    asm volatile("cp.async.cg.shared.global [%0],[%1],16;" :: "r"(s), "l"(g));
}
__device__ __forceinline__ void cpa_commit() {
    asm volatile("cp.async.commit_group;");
}
template <int N>
__device__ __forceinline__ void cpa_wait() {
    asm volatile("cp.async.wait_group %0;" :: "n"(N));
}

// ---------------------------------------------------------------------------
// fused input split: {Fm, Fs, Fq} fp32 -> bf16 (hi, lo)
// ---------------------------------------------------------------------------
#define SEG4 (MTOT * DMODEL / 4)

__global__ __launch_bounds__(256)
void split_in_kernel(const float* __restrict__ Fm, const float* __restrict__ Fs,
                     const float* __restrict__ Fq)
{
    const int i = blockIdx.x * 256 + threadIdx.x;
    if (i >= 3 * SEG4) return;
    const int seg = i / SEG4;
    const int off = i - seg * SEG4;
    const float* src = (seg == 0) ? Fm : (seg == 1) ? Fs : Fq;
    __nv_bfloat16* dh = (seg == 0) ? g_fmh : (seg == 1) ? g_fsh : g_fqh;
    __nv_bfloat16* dl = (seg == 0) ? g_fml : (seg == 1) ? g_fsl : g_fql;
    const float4 v = *(const float4*)(src + (size_t)off * 4);
    __nv_bfloat16 h0, h1, h2, h3, l0, l1, l2, l3;
    split2(v.x, h0, l0); split2(v.y, h1, l1);
    split2(v.z, h2, l2); split2(v.w, h3, l3);
    *(__nv_bfloat162*)(dh + (size_t)off * 4)     = __nv_bfloat162(h0, h1);
    *(__nv_bfloat162*)(dh + (size_t)off * 4 + 2) = __nv_bfloat162(h2, h3);
    *(__nv_bfloat162*)(dl + (size_t)off * 4)     = __nv_bfloat162(l0, l1);
    *(__nv_bfloat162*)(dl + (size_t)off * 4 + 2) = __nv_bfloat162(l2, l3);
}

// ---------------------------------------------------------------------------
// fused weight split: {Wq(scaled by QSC), Wk, Wv, w1, w2} fp32 -> bf16 (hi,lo)
// ---------------------------------------------------------------------------
#define WQ4 (3 * DMODEL * DMODEL / 4)
#define W14 (3 * DHID * DMODEL / 4)
#define WTOT4 (3 * WQ4 + 2 * W14)

__global__ __launch_bounds__(256)
void split_w_kernel(const float* __restrict__ Wq, const float* __restrict__ Wk,
                    const float* __restrict__ Wv, const float* __restrict__ w1,
                    const float* __restrict__ w2)
{
    const int i = blockIdx.x * 256 + threadIdx.x;
    if (i >= WTOT4) return;
    const float* src; __nv_bfloat16 *dh, *dl; int off; float sc = 1.f;
    if (i < WQ4)                 { src = Wq; dh = g_wqh; dl = g_wql; off = i; sc = QSC; }
    else if (i < 2 * WQ4)        { src = Wk; dh = g_wkh; dl = g_wkl; off = i - WQ4; }
    else if (i < 3 * WQ4)        { src = Wv; dh = g_wvh; dl = g_wvl; off = i - 2 * WQ4; }
    else if (i < 3 * WQ4 + W14)  { src = w1; dh = g_w1h; dl = g_w1l; off = i - 3 * WQ4; }
    else                         { src = w2; dh = g_w2h; dl = g_w2l; off = i - 3 * WQ4 - W14; }
    float4 v = *(const float4*)(src + (size_t)off * 4);
    v.x *= sc; v.y *= sc; v.z *= sc; v.w *= sc;
    __nv_bfloat16 h0, h1, h2, h3, l0, l1, l2, l3;
    split2(v.x, h0, l0); split2(v.y, h1, l1);
    split2(v.z, h2, l2); split2(v.w, h3, l3);
    *(__nv_bfloat162*)(dh + (size_t)off * 4)     = __nv_bfloat162(h0, h1);
    *(__nv_bfloat162*)(dh + (size_t)off * 4 + 2) = __nv_bfloat162(h2, h3);
    *(__nv_bfloat162*)(dl + (size_t)off * 4)     = __nv_bfloat162(l0, l1);
    *(__nv_bfloat162*)(dl + (size_t)off * 4 + 2) = __nv_bfloat162(l2, l3);
}

// ---------------------------------------------------------------------------
// bf16 3-pass split GEMM body (validated R10 inner loop)
// OUT: 0 -> fp32 C;  1 -> relu + bf16 split (Ch, Cl);  2 -> bf16 (Ch only)
// ---------------------------------------------------------------------------
#define TBM 128
#define TBN 128
#define TBK 32
#define TAS 40
#define REGB  (TBM * TAS * 2)
#define BUFSZ (4 * REGB)
#define GEMM_SMEM (2 * BUFSZ)

extern __shared__ char gsm[];

template <int OUT>
__device__ __forceinline__
void gemm_body(const __nv_bfloat16* __restrict__ Agh, const __nv_bfloat16* __restrict__ Agl,
               const __nv_bfloat16* __restrict__ Bgh, const __nv_bfloat16* __restrict__ Bgl,
               float* __restrict__ C, __nv_bfloat16* __restrict__ Ch,
               __nv_bfloat16* __restrict__ Cl, int M, int N, int K)
{
    const int tid  = threadIdx.x;
    const int lane = tid & 31;
    const int wid  = tid >> 5;
    const int wm   = wid & 1;
    const int wn   = wid >> 1;
    const int bm   = blockIdx.y * TBM;
    const int bn   = blockIdx.x * TBN;

    const uint32_t sbase = sptr(gsm);

    auto load_tile = [&](int buf, int k0) {
        const uint32_t b = sbase + buf * BUFSZ;
#pragma unroll
        for (int j = 0; j < 4; ++j) {
            const int c = tid + j * 128;
            const int row = c >> 2, kc = (c & 3) << 3;
            const uint32_t so = (uint32_t)(row * TAS + kc) * 2;
            const size_t goA = (size_t)(bm + row) * K + k0 + kc;
            const size_t goB = (size_t)(bn + row) * K + k0 + kc;
            cpa16(b + so,            Agh + goA);
            cpa16(b + REGB + so,     Agl + goA);
            cpa16(b + 2 * REGB + so, Bgh + goB);
            cpa16(b + 3 * REGB + so, Bgl + goB);
        }
        cpa_commit();
    };

    float c[4][8][4];
#pragma unroll
    for (int mi = 0; mi < 4; ++mi)
#pragma unroll
        for (int ni = 0; ni < 8; ++ni)
#pragma unroll
            for (int e = 0; e < 4; ++e) c[mi][ni][e] = 0.f;

    const int lmA = lane & 15;
    const int lkA = (lane >> 4) << 3;
    const int lnB = ((lane >> 4) & 1) * 8 + (lane & 7);
    const int lkB = ((lane >> 3) & 1) * 8;
    const uint32_t relA = (uint32_t)((wm * 64 + lmA) * TAS + lkA) * 2;
    const uint32_t relB = (uint32_t)((wn * 64 + lnB) * TAS + lkB) * 2;

    const int niter = K / TBK;
    load_tile(0, 0);

    for (int it = 0; it < niter; ++it) {
        const int cur = it & 1;
        if (it + 1 < niter) { load_tile(cur ^ 1, (it + 1) * TBK); cpa_wait<1>(); }
        else cpa_wait<0>();
        __syncthreads();

        const uint32_t b = sbase + cur * BUFSZ;
        const uint32_t aAh = b + relA,            aAl = b + REGB + relA;
        const uint32_t aBh = b + 2 * REGB + relB, aBl = b + 3 * REGB + relB;

#pragma unroll
        for (int ks = 0; ks < 2; ++ks) {
            const uint32_t ko = ks * 32;
            uint32_t bhf[8][2], blf[8][2];
#pragma unroll
            for (int p = 0; p < 4; ++p) {
                ldm4(aBh + p * (16 * TAS * 2) + ko,
                     bhf[2*p][0], bhf[2*p][1], bhf[2*p+1][0], bhf[2*p+1][1]);
                ldm4(aBl + p * (16 * TAS * 2) + ko,
                     blf[2*p][0], blf[2*p][1], blf[2*p+1][0], blf[2*p+1][1]);
            }
#pragma unroll
            for (int mi = 0; mi < 4; ++mi) {
                uint32_t ah[4], al[4];
                ldm4(aAh + mi * (16 * TAS * 2) + ko, ah[0], ah[1], ah[2], ah[3]);
                ldm4(aAl + mi * (16 * TAS * 2) + ko, al[0], al[1], al[2], al[3]);
#pragma unroll
                for (int ni = 0; ni < 8; ++ni) mma_bf16(c[mi][ni], ah, bhf[ni]);
#pragma unroll
                for (int ni = 0; ni < 8; ++ni) mma_bf16(c[mi][ni], ah, blf[ni]);
#pragma unroll
                for (int ni = 0; ni < 8; ++ni) mma_bf16(c[mi][ni], al, bhf[ni]);
            }
        }
        __syncthreads();
    }

#pragma unroll
    for (int mi = 0; mi < 4; ++mi) {
        const int row0 = bm + wm * 64 + mi * 16 + (lane >> 2);
#pragma unroll
        for (int ni = 0; ni < 8; ++ni) {
            const int col = bn + wn * 64 + ni * 8 + ((lane & 3) << 1);
            float v0 = c[mi][ni][0], v1 = c[mi][ni][1];
            float v2 = c[mi][ni][2], v3 = c[mi][ni][3];
            if (OUT == 0) {
                float2 a; a.x = v0; a.y = v1;
                float2 bq; bq.x = v2; bq.y = v3;
                *(float2*)&C[(size_t)row0 * N + col]       = a;
                *(float2*)&C[(size_t)(row0 + 8) * N + col] = bq;
            } else if (OUT == 1) {
                v0 = fmaxf(v0, 0.f); v1 = fmaxf(v1, 0.f);
                v2 = fmaxf(v2, 0.f); v3 = fmaxf(v3, 0.f);
                __nv_bfloat16 h0, h1, h2, h3, l0, l1, l2, l3;
                split2(v0, h0, l0); split2(v1, h1, l1);
                split2(v2, h2, l2); split2(v3, h3, l3);
                *(__nv_bfloat162*)&Ch[(size_t)row0 * N + col]       = __nv_bfloat162(h0, h1);
                *(__nv_bfloat162*)&Cl[(size_t)row0 * N + col]       = __nv_bfloat162(l0, l1);
                *(__nv_bfloat162*)&Ch[(size_t)(row0 + 8) * N + col] = __nv_bfloat162(h2, h3);
                *(__nv_bfloat162*)&Cl[(size_t)(row0 + 8) * N + col] = __nv_bfloat162(l2, l3);
            } else {
                *(__nv_bfloat162*)&Ch[(size_t)row0 * N + col] =
                    __nv_bfloat162(__float2bfloat16(v0), __float2bfloat16(v1));
                *(__nv_bfloat162*)&Ch[(size_t)(row0 + 8) * N + col] =
                    __nv_bfloat162(__float2bfloat16(v2), __float2bfloat16(v3));
            }
        }
    }
}

template <int OUT>
__global__ __launch_bounds__(128, 2)
void gemm_bf(const __nv_bfloat16* __restrict__ Agh, const __nv_bfloat16* __restrict__ Agl,
             const __nv_bfloat16* __restrict__ Bgh, const __nv_bfloat16* __restrict__ Bgl,
             float* __restrict__ C, __nv_bfloat16* __restrict__ Ch,
             __nv_bfloat16* __restrict__ Cl, int M, int N, int K)
{
    gemm_body<OUT>(Agh, Agl, Bgh, Bgl, C, Ch, Cl, M, N, K);
}

// fused QKV projection: grid.z selects {Q, K, V}; bf16 output
__global__ __launch_bounds__(128, 2)
void gemm_qkv(const __nv_bfloat16* __restrict__ A0h, const __nv_bfloat16* __restrict__ A0l,
              const __nv_bfloat16* __restrict__ A1h, const __nv_bfloat16* __restrict__ A1l,
              const __nv_bfloat16* __restrict__ A2h, const __nv_bfloat16* __restrict__ A2l,
              const __nv_bfloat16* __restrict__ W0h, const __nv_bfloat16* __restrict__ W0l,
              const __nv_bfloat16* __restrict__ W1h, const __nv_bfloat16* __restrict__ W1l,
              const __nv_bfloat16* __restrict__ W2h, const __nv_bfloat16* __restrict__ W2l,
              __nv_bfloat16* __restrict__ Cq, __nv_bfloat16* __restrict__ Ck,
              __nv_bfloat16* __restrict__ Cv)
{
    const __nv_bfloat16 *Ah, *Al, *Bh, *Bl;
    __nv_bfloat16* Co;
    if (blockIdx.z == 0)      { Ah = A0h; Al = A0l; Bh = W0h; Bl = W0l; Co = Cq; }
    else if (blockIdx.z == 1) { Ah = A1h; Al = A1l; Bh = W1h; Bl = W1l; Co = Ck; }
    else                      { Ah = A2h; Al = A2l; Bh = W2h; Bl = W2l; Co = Cv; }
    gemm_body<2>(Ah, Al, Bh, Bl, nullptr, Co, nullptr, MTOT, DMODEL, DMODEL);
}

// ---------------------------------------------------------------------------
// Tensor-core flash attention — bf16 in, V row-major + ldmatrix.trans for PV
// ---------------------------------------------------------------------------
#define FM  64
#define FN  64
#define FQS 264
#define FA_SMEM_BYTES (3 * FM * FQS * 2)    // Qs + Ks + Vs = 101376

extern __shared__ char fa_raw[];

__global__ __launch_bounds__(128, 2)
void flash_tc(const __nv_bfloat16* __restrict__ Q, const __nv_bfloat16* __restrict__ K,
              const __nv_bfloat16* __restrict__ V, float* __restrict__ O)
{
    __nv_bfloat16* Qs = (__nv_bfloat16*)fa_raw;     // [64][FQS]
    __nv_bfloat16* Ks = Qs + FM * FQS;              // [64][FQS]
    __nv_bfloat16* Vs = Ks + FN * FQS;              // [64][FQS] row-major (k, d)

    const int tid  = threadIdx.x;
    const int lane = tid & 31;
    const int w    = tid >> 5;
    const int qbase = blockIdx.x * FM;
    const int h = blockIdx.y, b = blockIdx.z;
    const size_t bstride = (size_t)SEQ * DMODEL;
    const __nv_bfloat16* Qb = Q + b * bstride + h * GSZ;
    const __nv_bfloat16* Kb = K + b * bstride + h * GSZ;
    const __nv_bfloat16* Vb = V + b * bstride + h * GSZ;

    const int lmA = lane & 15;
    const int lkA = (lane >> 4) << 3;
    const int lnB = ((lane >> 4) & 1) * 8 + (lane & 7);
    const int lkB = ((lane >> 3) & 1) * 8;

    const uint32_t aQ = sptr(Qs) + (uint32_t)((w * 16 + lmA) * FQS + lkA) * 2;
    const uint32_t aK = sptr(Ks) + (uint32_t)(lnB * FQS + lkB) * 2;
    // trans-ldmatrix base for V: lane -> (k_row = lane&15, d_off = (lane>>4)*8)
    const uint32_t aV = sptr(Vs) + (uint32_t)((lane & 15) * FQS + (lane >> 4) * 8) * 2;

    // stage Q: straight bf16 copy (scale pre-folded into Wq)
#pragma unroll
    for (int j = 0; j < 16; ++j) {
        const int idx = tid + j * 128;
        const int row = idx >> 5, c8 = idx & 31;
        const uint4 u = *(const uint4*)(Qb + (size_t)(qbase + row) * DMODEL + c8 * 8);
        *(uint4*)(Qs + row * FQS + c8 * 8) = u;
    }

    float mA = -1e30f, mB = -1e30f, lA = 0.f, lB = 0.f;
    float o[32][4];
#pragma unroll
    for (int f = 0; f < 32; ++f)
#pragma unroll
        for (int e = 0; e < 4; ++e) o[f][e] = 0.f;

    for (int kb = 0; kb < SEQ; kb += FN) {
        __syncthreads();
        // stage K and V: straight bf16 copies (row-major, stride FQS)
#pragma unroll
        for (int j = 0; j < 16; ++j) {
            const int idx = tid + j * 128;
            const int row = idx >> 5, c8 = idx & 31;
            const uint4 uk = *(const uint4*)(Kb + (size_t)(kb + row) * DMODEL + c8 * 8);
            *(uint4*)(Ks + row * FQS + c8 * 8) = uk;
            const uint4 uv = *(const uint4*)(Vb + (size_t)(kb + row) * DMODEL + c8 * 8);
            *(uint4*)(Vs + row * FQS + c8 * 8) = uv;
        }
        __syncthreads();

        float s[8][4];
#pragma unroll
        for (int f = 0; f < 8; ++f)
#pragma unroll
            for (int e = 0; e < 4; ++e) s[f][e] = 0.f;

#pragma unroll
        for (int ks = 0; ks < 16; ++ks) {
            uint32_t af[4];
            ldm4(aQ + ks * 32, af[0], af[1], af[2], af[3]);
#pragma unroll
            for (int g = 0; g < 4; ++g) {
                uint32_t b0[2], b1[2];
                ldm4(aK + (uint32_t)(g * 16 * FQS) * 2 + ks * 32,
                     b0[0], b0[1], b1[0], b1[1]);
                mma_bf16(s[2 * g],     af, b0);
                mma_bf16(s[2 * g + 1], af, b1);
            }
        }

        float mxA = -1e30f, mxB = -1e30f;
#pragma unroll
        for (int f = 0; f < 8; ++f) {
            mxA = fmaxf(mxA, fmaxf(s[f][0], s[f][1]));
            mxB = fmaxf(mxB, fmaxf(s[f][2], s[f][3]));
        }
        mxA = fmaxf(mxA, __shfl_xor_sync(0xffffffffu, mxA, 1));
        mxA = fmaxf(mxA, __shfl_xor_sync(0xffffffffu, mxA, 2));
        mxB = fmaxf(mxB, __shfl_xor_sync(0xffffffffu, mxB, 1));
        mxB = fmaxf(mxB, __shfl_xor_sync(0xffffffffu, mxB, 2));
        const float mnA = fmaxf(mA, mxA);
        const float mnB = fmaxf(mB, mxB);
        float sumA = 0.f, sumB = 0.f;
#pragma unroll
        for (int f = 0; f < 8; ++f) {
            s[f][0] = e2(s[f][0] - mnA); s[f][1] = e2(s[f][1] - mnA);
            s[f][2] = e2(s[f][2] - mnB); s[f][3] = e2(s[f][3] - mnB);
            sumA += s[f][0] + s[f][1];
            sumB += s[f][2] + s[f][3];
        }
        sumA += __shfl_xor_sync(0xffffffffu, sumA, 1);
        sumA += __shfl_xor_sync(0xffffffffu, sumA, 2);
        sumB += __shfl_xor_sync(0xffffffffu, sumB, 1);
        sumB += __shfl_xor_sync(0xffffffffu, sumB, 2);
        const float ccA = e2(mA - mnA);
        const float ccB = e2(mB - mnB);
        lA = lA * ccA + sumA; mA = mnA;
        lB = lB * ccB + sumB; mB = mnB;

#pragma unroll
        for (int f = 0; f < 32; ++f) {
            o[f][0] *= ccA; o[f][1] *= ccA;
            o[f][2] *= ccB; o[f][3] *= ccB;
        }

        // O += P @ V; B fragments via ldmatrix.trans from row-major Vs[k][d]
#pragma unroll
        for (int kf = 0; kf < 4; ++kf) {
            uint32_t ap[4];
            ap[0] = packbf(s[2 * kf][0],     s[2 * kf][1]);
            ap[1] = packbf(s[2 * kf][2],     s[2 * kf][3]);
            ap[2] = packbf(s[2 * kf + 1][0], s[2 * kf + 1][1]);
            ap[3] = packbf(s[2 * kf + 1][2], s[2 * kf + 1][3]);
            const uint32_t aVk = aV + (uint32_t)(kf * 16 * FQS) * 2;
#pragma unroll
            for (int g = 0; g < 16; ++g) {
                uint32_t b0[2], b1[2];
                ldm4t(aVk + g * 32, b0[0], b0[1], b1[0], b1[1]);
                mma_bf16(o[2 * g],     ap, b0);
                mma_bf16(o[2 * g + 1], ap, b1);
            }
        }
    }

    const float liA = 1.f / lA;
    const float liB = 1.f / lB;
    const int rowA = qbase + w * 16 + (lane >> 2);
    float* Ob = O + b * bstride + h * GSZ;
#pragma unroll
    for (int f = 0; f < 32; ++f) {
        const int col = f * 8 + ((lane & 3) << 1);
        float2 rA; rA.x = o[f][0] * liA; rA.y = o[f][1] * liA;
        float2 rB; rB.x = o[f][2] * liB; rB.y = o[f][3] * liB;
        *(float2*)&Ob[(size_t)rowA * DMODEL + col]       = rA;
        *(float2*)&Ob[(size_t)(rowA + 8) * DMODEL + col] = rB;
    }
}

// ---------------------------------------------------------------------------
// out = LayerNorm(X + R); optionally emit bf16 (hi, lo) split
// ---------------------------------------------------------------------------
__global__ __launch_bounds__(128)
void add_ln_kernel(const float* __restrict__ X, const float* __restrict__ R,
                   const float* __restrict__ g, const float* __restrict__ bt,
                   float eps, float* __restrict__ out,
                   __nv_bfloat16* __restrict__ oh, __nv_bfloat16* __restrict__ ol,
                   int doSplit)
{
    const int row = blockIdx.x;
    const int tid = threadIdx.x;
    float4 v = *(const float4*)(X + (size_t)row * DMODEL + tid * 4);
    const float4 rr = *(const float4*)(R + (size_t)row * DMODEL + tid * 4);
    v.x += rr.x; v.y += rr.y; v.z += rr.z; v.w += rr.w;
    float s  = v.x + v.y + v.z + v.w;
    float sq = v.x * v.x + v.y * v.y + v.z * v.z + v.w * v.w;
#pragma unroll
    for (int off = 16; off; off >>= 1) {
        s  += __shfl_xor_sync(0xffffffffu, s,  off);
        sq += __shfl_xor_sync(0xffffffffu, sq, off);
    }
    __shared__ float ssum[4], ssq[4];
    const int w = tid >> 5, l = tid & 31;
    if (l == 0) { ssum[w] = s; ssq[w] = sq; }
    __syncthreads();
    s  = ssum[0] + ssum[1] + ssum[2] + ssum[3];
    sq = ssq[0]  + ssq[1]  + ssq[2]  + ssq[3];
    const float mean = s * (1.f / DMODEL);
    const float var  = sq * (1.f / DMODEL) - mean * mean;
    const float rstd = rsqrtf(var + eps);
    const float4 gg = *(const float4*)(g  + tid * 4);
    const float4 bb = *(const float4*)(bt + tid * 4);
    float4 r;
    r.x = (v.x - mean) * rstd * gg.x + bb.x;
    r.y = (v.y - mean) * rstd * gg.y + bb.y;
    r.z = (v.z - mean) * rstd * gg.z + bb.z;
    r.w = (v.w - mean) * rstd * gg.w + bb.w;
    *(float4*)(out + (size_t)row * DMODEL + tid * 4) = r;
    if (doSplit) {
        __nv_bfloat16 h0, h1, h2, h3, l0, l1, l2, l3;
        split2(r.x, h0, l0); split2(r.y, h1, l1);
        split2(r.z, h2, l2); split2(r.w, h3, l3);
        const size_t o = (size_t)row * DMODEL + tid * 4;
        *(__nv_bfloat162*)(oh + o)     = __nv_bfloat162(h0, h1);
        *(__nv_bfloat162*)(oh + o + 2) = __nv_bfloat162(h2, h3);
        *(__nv_bfloat162*)(ol + o)     = __nv_bfloat162(l0, l1);
        *(__nv_bfloat162*)(ol + o + 2) = __nv_bfloat162(l2, l3);
    }
}

// ---------------------------------------------------------------------------
// host side
// ---------------------------------------------------------------------------
extern "C" void kernel_launch(void* const* d_in, const int* in_sizes, int n_in,
                              void* d_out, int out_size)
{
    (void)in_sizes; (void)n_in; (void)out_size;
    const float* Fm   = (const float*)d_in[0];
    const float* Fs   = (const float*)d_in[1];
    const float* Fq   = (const float*)d_in[2];
    const float* Wq   = (const float*)d_in[3];
    const float* Wk   = (const float*)d_in[4];
    const float* Wv   = (const float*)d_in[5];
    const float* lng  = (const float*)d_in[6];
    const float* lnb  = (const float*)d_in[7];
    const float* w1   = (const float*)d_in[8];
    const float* w2   = (const float*)d_in[9];
    const float* flg  = (const float*)d_in[10];
    const float* flb  = (const float*)d_in[11];
    float* out = (float*)d_out;

    float *att, *x, *y, *css, *cqq;
    cudaGetSymbolAddress((void**)&att, g_att);
    cudaGetSymbolAddress((void**)&x,   g_x);
    cudaGetSymbolAddress((void**)&y,   g_y);
    cudaGetSymbolAddress((void**)&css, g_css);
    cudaGetSymbolAddress((void**)&cqq, g_cqq);

    __nv_bfloat16 *qb, *kb, *vb;
    __nv_bfloat16 *wqh, *wql, *wkh, *wkl, *wvh, *wvl, *w1h, *w1l, *w2h, *w2l;
    __nv_bfloat16 *fmh, *fml, *fsh, *fsl, *fqh, *fql;
    __nv_bfloat16 *cssh, *cssl, *cqqh, *cqql, *xh, *xl, *hh, *hl;
    cudaGetSymbolAddress((void**)&qb, g_qb);
    cudaGetSymbolAddress((void**)&kb, g_kb);
    cudaGetSymbolAddress((void**)&vb, g_vb);
    cudaGetSymbolAddress((void**)&wqh, g_wqh); cudaGetSymbolAddress((void**)&wql, g_wql);
    cudaGetSymbolAddress((void**)&wkh, g_wkh); cudaGetSymbolAddress((void**)&wkl, g_wkl);
    cudaGetSymbolAddress((void**)&wvh, g_wvh); cudaGetSymbolAddress((void**)&wvl, g_wvl);
    cudaGetSymbolAddress((void**)&w1h, g_w1h); cudaGetSymbolAddress((void**)&w1l, g_w1l);
    cudaGetSymbolAddress((void**)&w2h, g_w2h); cudaGetSymbolAddress((void**)&w2l, g_w2l);
    cudaGetSymbolAddress((void**)&fmh, g_fmh); cudaGetSymbolAddress((void**)&fml, g_fml);
    cudaGetSymbolAddress((void**)&fsh, g_fsh); cudaGetSymbolAddress((void**)&fsl, g_fsl);
    cudaGetSymbolAddress((void**)&fqh, g_fqh); cudaGetSymbolAddress((void**)&fql, g_fql);
    cudaGetSymbolAddress((void**)&cssh, g_cssh); cudaGetSymbolAddress((void**)&cssl, g_cssl);
    cudaGetSymbolAddress((void**)&cqqh, g_cqqh); cudaGetSymbolAddress((void**)&cqql, g_cqql);
    cudaGetSymbolAddress((void**)&xh, g_xh);   cudaGetSymbolAddress((void**)&xl, g_xl);
    cudaGetSymbolAddress((void**)&hh, g_hh);   cudaGetSymbolAddress((void**)&hl, g_hl);

    cudaFuncSetAttribute(flash_tc, cudaFuncAttributeMaxDynamicSharedMemorySize,
                         FA_SMEM_BYTES);
    cudaFuncSetAttribute(gemm_bf<0>, cudaFuncAttributeMaxDynamicSharedMemorySize,
                         GEMM_SMEM);
    cudaFuncSetAttribute(gemm_bf<1>, cudaFuncAttributeMaxDynamicSharedMemorySize,
                         GEMM_SMEM);
    cudaFuncSetAttribute(gemm_qkv, cudaFuncAttributeMaxDynamicSharedMemorySize,
                         GEMM_SMEM);

    // fused preprocessing (2 launches); Wq pre-scaled by QSC
    split_in_kernel<<<(3 * SEG4 + 255) / 256, 256>>>(Fm, Fs, Fq);
    split_w_kernel<<<(WTOT4 + 255) / 256, 256>>>(Wq, Wk, Wv, w1, w2);

    const dim3 gqkv(DMODEL / TBN, MTOT / TBM, 3);
    const dim3 gp(DMODEL / TBN, MTOT / TBM);
    const dim3 gh(DHID / TBN,   MTOT / TBM);
    const dim3 ga(SEQ / FM, NHEADS, BATCH);

    auto run_block = [&](int i,
                         const __nv_bfloat16* Qh, const __nv_bfloat16* Ql,
                         const __nv_bfloat16* Kh, const __nv_bfloat16* Kl,
                         const __nv_bfloat16* Vh, const __nv_bfloat16* Vl,
                         const float* Rp, float* op,
                         __nv_bfloat16* oph, __nv_bfloat16* opl, int splitOut) {
        const size_t wOff  = (size_t)i * DMODEL * DMODEL;
        const size_t w1Off = (size_t)i * DHID * DMODEL;
        gemm_qkv<<<gqkv, 128, GEMM_SMEM>>>(Qh, Ql, Kh, Kl, Vh, Vl,
                                           wqh + wOff, wql + wOff,
                                           wkh + wOff, wkl + wOff,
                                           wvh + wOff, wvl + wOff,
                                           qb, kb, vb);
        flash_tc<<<ga, 128, FA_SMEM_BYTES>>>(qb, kb, vb, att);
        add_ln_kernel<<<MTOT, 128>>>(att, Rp, lng + i * DMODEL, lnb + i * DMODEL,
                                     1e-5f, x, xh, xl, 1);
        gemm_bf<1><<<gh, 128, GEMM_SMEM>>>(xh, xl, w1h + w1Off, w1l + w1Off,
                                           nullptr, hh, hl, MTOT, DHID, DMODEL);
        gemm_bf<0><<<gp, 128, GEMM_SMEM>>>(hh, hl, w2h + w1Off, w2l + w1Off,
                                           y, nullptr, nullptr, MTOT, DMODEL, DHID);
        add_ln_kernel<<<MTOT, 128>>>(y, x, flg + i * DMODEL, flb + i * DMODEL,
                                     1e-6f, op, oph, opl, splitOut);
    };

    // css = blk(0, Fs, Fs, Fm, Fm); cqq = blk(1, Fq, Fq, Fq, Fq);
    // csq = blk(2, cqq, Fs, css, css)
    run_block(0, fsh, fsl, fsh, fsl, fmh, fml, Fm, css, cssh, cssl, 1);
    run_block(1, fqh, fql, fqh, fql, fqh, fql, Fq, cqq, cqqh, cqql, 1);
    run_block(2, cqqh, cqql, fsh, fsl, cssh, cssl, css, out, nullptr, nullptr, 0);
}

// round 16
// speedup vs baseline: 1.8212x; 1.0657x over previous
#include <cuda_runtime.h>
#include <cuda_bf16.h>
#include <cstdint>

// ---------------------------------------------------------------------------
// Problem constants
// ---------------------------------------------------------------------------
#define BATCH   4
#define SEQ     2048
#define DMODEL  512
#define DHID    2048
#define NHEADS  2
#define GSZ     256
#define MTOT    (BATCH * SEQ)       // 8192

// softmax scale folded into Wq: 1/sqrt(256) * log2(e)
#define QSC 0.09016994374947424f

// ---------------------------------------------------------------------------
// Scratch (device globals) — two sets so blocks 0 and 1 can run concurrently
// ---------------------------------------------------------------------------
__device__ __nv_bfloat16 g_qb[MTOT * DMODEL],  g_qb2[MTOT * DMODEL];
__device__ __nv_bfloat16 g_kb[MTOT * DMODEL],  g_kb2[MTOT * DMODEL];
__device__ __nv_bfloat16 g_vb[MTOT * DMODEL],  g_vb2[MTOT * DMODEL];
__device__ float g_att[MTOT * DMODEL], g_att2[MTOT * DMODEL];
__device__ float g_x  [MTOT * DMODEL], g_x2  [MTOT * DMODEL];
__device__ float g_y  [MTOT * DMODEL], g_y2  [MTOT * DMODEL];
__device__ float g_css[MTOT * DMODEL];
__device__ float g_cqq[MTOT * DMODEL];

__device__ __nv_bfloat16 g_wqh[3*DMODEL*DMODEL], g_wql[3*DMODEL*DMODEL];
__device__ __nv_bfloat16 g_wkh[3*DMODEL*DMODEL], g_wkl[3*DMODEL*DMODEL];
__device__ __nv_bfloat16 g_wvh[3*DMODEL*DMODEL], g_wvl[3*DMODEL*DMODEL];
__device__ __nv_bfloat16 g_w1h[3*DHID*DMODEL],   g_w1l[3*DHID*DMODEL];
__device__ __nv_bfloat16 g_w2h[3*DMODEL*DHID],   g_w2l[3*DMODEL*DHID];
__device__ __nv_bfloat16 g_fmh[MTOT*DMODEL], g_fml[MTOT*DMODEL];
__device__ __nv_bfloat16 g_fsh[MTOT*DMODEL], g_fsl[MTOT*DMODEL];
__device__ __nv_bfloat16 g_fqh[MTOT*DMODEL], g_fql[MTOT*DMODEL];
__device__ __nv_bfloat16 g_cssh[MTOT*DMODEL], g_cssl[MTOT*DMODEL];
__device__ __nv_bfloat16 g_cqqh[MTOT*DMODEL], g_cqql[MTOT*DMODEL];
__device__ __nv_bfloat16 g_xh[MTOT*DMODEL],  g_xl[MTOT*DMODEL];
__device__ __nv_bfloat16 g_xh2[MTOT*DMODEL], g_xl2[MTOT*DMODEL];
__device__ __nv_bfloat16 g_hh[MTOT*DHID],    g_hl[MTOT*DHID];
__device__ __nv_bfloat16 g_hh2[MTOT*DHID],   g_hl2[MTOT*DHID];

// ---------------------------------------------------------------------------
// helpers
// ---------------------------------------------------------------------------
__device__ __forceinline__ uint32_t sptr(const void* p) {
    return (uint32_t)__cvta_generic_to_shared(p);
}
__device__ __forceinline__ void ldm4(uint32_t a, uint32_t& r0, uint32_t& r1,
                                     uint32_t& r2, uint32_t& r3) {
    asm volatile("ldmatrix.sync.aligned.m8n8.x4.shared.b16 {%0,%1,%2,%3},[%4];"
                 : "=r"(r0), "=r"(r1), "=r"(r2), "=r"(r3) : "r"(a));
}
__device__ __forceinline__ void ldm4t(uint32_t a, uint32_t& r0, uint32_t& r1,
                                      uint32_t& r2, uint32_t& r3) {
    asm volatile("ldmatrix.sync.aligned.m8n8.x4.trans.shared.b16 {%0,%1,%2,%3},[%4];"
                 : "=r"(r0), "=r"(r1), "=r"(r2), "=r"(r3) : "r"(a));
}
__device__ __forceinline__ void mma_bf16(float c[4], const uint32_t a[4],
                                         const uint32_t b[2]) {
    asm volatile(
        "mma.sync.aligned.m16n8k16.row.col.f32.bf16.bf16.f32 "
        "{%0,%1,%2,%3},{%4,%5,%6,%7},{%8,%9},{%0,%1,%2,%3};"
        : "+f"(c[0]), "+f"(c[1]), "+f"(c[2]), "+f"(c[3])
        : "r"(a[0]), "r"(a[1]), "r"(a[2]), "r"(a[3]), "r"(b[0]), "r"(b[1]));
}
__device__ __forceinline__ float e2(float x) {
    float y; asm("ex2.approx.ftz.f32 %0,%1;" : "=f"(y) : "f"(x)); return y;
}
__device__ __forceinline__ uint32_t packbf(float a, float b) {
    const __nv_bfloat162 t = __float22bfloat162_rn(make_float2(a, b));
    return *reinterpret_cast<const uint32_t*>(&t);
}
__device__ __forceinline__ void split2(float v, __nv_bfloat16& h, __nv_bfloat16& l) {
    h = __float2bfloat16(v);
    l = __float2bfloat16(v - __bfloat162float(h));
}
__device__ __forceinline__ void cpa16(uint32_t s, const void* g) {
    asm volatile("cp.async.cg.shared.global [%0],[%1],16;" :: "r"(s), "l"(g));
}
__device__ __forceinline__ void cpa_commit() {
    asm volatile("cp.async.commit_group;");
}
template <int N>
__device__ __forceinline__ void cpa_wait() {
    asm volatile("cp.async.wait_group %0;" :: "n"(N));
}

// ---------------------------------------------------------------------------
// fused input split: {Fm, Fs, Fq} fp32 -> bf16 (hi, lo)
// ---------------------------------------------------------------------------
#define SEG4 (MTOT * DMODEL / 4)

__global__ __launch_bounds__(256)
void split_in_kernel(const float* __restrict__ Fm, const float* __restrict__ Fs,
                     const float* __restrict__ Fq)
{
    const int i = blockIdx.x * 256 + threadIdx.x;
    if (i >= 3 * SEG4) return;
    const int seg = i / SEG4;
    const int off = i - seg * SEG4;
    const float* src = (seg == 0) ? Fm : (seg == 1) ? Fs : Fq;
    __nv_bfloat16* dh = (seg == 0) ? g_fmh : (seg == 1) ? g_fsh : g_fqh;
    __nv_bfloat16* dl = (seg == 0) ? g_fml : (seg == 1) ? g_fsl : g_fql;
    const float4 v = *(const float4*)(src + (size_t)off * 4);
    __nv_bfloat16 h0, h1, h2, h3, l0, l1, l2, l3;
    split2(v.x, h0, l0); split2(v.y, h1, l1);
    split2(v.z, h2, l2); split2(v.w, h3, l3);
    *(__nv_bfloat162*)(dh + (size_t)off * 4)     = __nv_bfloat162(h0, h1);
    *(__nv_bfloat162*)(dh + (size_t)off * 4 + 2) = __nv_bfloat162(h2, h3);
    *(__nv_bfloat162*)(dl + (size_t)off * 4)     = __nv_bfloat162(l0, l1);
    *(__nv_bfloat162*)(dl + (size_t)off * 4 + 2) = __nv_bfloat162(l2, l3);
}

// ---------------------------------------------------------------------------
// fused weight split: {Wq(scaled by QSC), Wk, Wv, w1, w2} fp32 -> bf16 (hi,lo)
// ---------------------------------------------------------------------------
#define WQ4 (3 * DMODEL * DMODEL / 4)
#define W14 (3 * DHID * DMODEL / 4)
#define WTOT4 (3 * WQ4 + 2 * W14)

__global__ __launch_bounds__(256)
void split_w_kernel(const float* __restrict__ Wq, const float* __restrict__ Wk,
                    const float* __restrict__ Wv, const float* __restrict__ w1,
                    const float* __restrict__ w2)
{
    const int i = blockIdx.x * 256 + threadIdx.x;
    if (i >= WTOT4) return;
    const float* src; __nv_bfloat16 *dh, *dl; int off; float sc = 1.f;
    if (i < WQ4)                 { src = Wq; dh = g_wqh; dl = g_wql; off = i; sc = QSC; }
    else if (i < 2 * WQ4)        { src = Wk; dh = g_wkh; dl = g_wkl; off = i - WQ4; }
    else if (i < 3 * WQ4)        { src = Wv; dh = g_wvh; dl = g_wvl; off = i - 2 * WQ4; }
    else if (i < 3 * WQ4 + W14)  { src = w1; dh = g_w1h; dl = g_w1l; off = i - 3 * WQ4; }
    else                         { src = w2; dh = g_w2h; dl = g_w2l; off = i - 3 * WQ4 - W14; }
    float4 v = *(const float4*)(src + (size_t)off * 4);
    v.x *= sc; v.y *= sc; v.z *= sc; v.w *= sc;
    __nv_bfloat16 h0, h1, h2, h3, l0, l1, l2, l3;
    split2(v.x, h0, l0); split2(v.y, h1, l1);
    split2(v.z, h2, l2); split2(v.w, h3, l3);
    *(__nv_bfloat162*)(dh + (size_t)off * 4)     = __nv_bfloat162(h0, h1);
    *(__nv_bfloat162*)(dh + (size_t)off * 4 + 2) = __nv_bfloat162(h2, h3);
    *(__nv_bfloat162*)(dl + (size_t)off * 4)     = __nv_bfloat162(l0, l1);
    *(__nv_bfloat162*)(dl + (size_t)off * 4 + 2) = __nv_bfloat162(l2, l3);
}

// ---------------------------------------------------------------------------
// bf16 3-pass split GEMM body (validated R10 inner loop)
// OUT: 0 -> fp32 C;  1 -> relu + bf16 split (Ch, Cl);  2 -> bf16 (Ch only)
// ---------------------------------------------------------------------------
#define TBM 128
#define TBN 128
#define TBK 32
#define TAS 40
#define REGB  (TBM * TAS * 2)
#define BUFSZ (4 * REGB)
#define GEMM_SMEM (2 * BUFSZ)

extern __shared__ char gsm[];

template <int OUT>
__device__ __forceinline__
void gemm_body(const __nv_bfloat16* __restrict__ Agh, const __nv_bfloat16* __restrict__ Agl,
               const __nv_bfloat16* __restrict__ Bgh, const __nv_bfloat16* __restrict__ Bgl,
               float* __restrict__ C, __nv_bfloat16* __restrict__ Ch,
               __nv_bfloat16* __restrict__ Cl, int M, int N, int K)
{
    const int tid  = threadIdx.x;
    const int lane = tid & 31;
    const int wid  = tid >> 5;
    const int wm   = wid & 1;
    const int wn   = wid >> 1;
    const int bm   = blockIdx.y * TBM;
    const int bn   = blockIdx.x * TBN;

    const uint32_t sbase = sptr(gsm);

    auto load_tile = [&](int buf, int k0) {
        const uint32_t b = sbase + buf * BUFSZ;
#pragma unroll
        for (int j = 0; j < 4; ++j) {
            const int c = tid + j * 128;
            const int row = c >> 2, kc = (c & 3) << 3;
            const uint32_t so = (uint32_t)(row * TAS + kc) * 2;
            const size_t goA = (size_t)(bm + row) * K + k0 + kc;
            const size_t goB = (size_t)(bn + row) * K + k0 + kc;
            cpa16(b + so,            Agh + goA);
            cpa16(b + REGB + so,     Agl + goA);
            cpa16(b + 2 * REGB + so, Bgh + goB);
            cpa16(b + 3 * REGB + so, Bgl + goB);
        }
        cpa_commit();
    };

    float c[4][8][4];
#pragma unroll
    for (int mi = 0; mi < 4; ++mi)
#pragma unroll
        for (int ni = 0; ni < 8; ++ni)
#pragma unroll
            for (int e = 0; e < 4; ++e) c[mi][ni][e] = 0.f;

    const int lmA = lane & 15;
    const int lkA = (lane >> 4) << 3;
    const int lnB = ((lane >> 4) & 1) * 8 + (lane & 7);
    const int lkB = ((lane >> 3) & 1) * 8;
    const uint32_t relA = (uint32_t)((wm * 64 + lmA) * TAS + lkA) * 2;
    const uint32_t relB = (uint32_t)((wn * 64 + lnB) * TAS + lkB) * 2;

    const int niter = K / TBK;
    load_tile(0, 0);

    for (int it = 0; it < niter; ++it) {
        const int cur = it & 1;
        if (it + 1 < niter) { load_tile(cur ^ 1, (it + 1) * TBK); cpa_wait<1>(); }
        else cpa_wait<0>();
        __syncthreads();

        const uint32_t b = sbase + cur * BUFSZ;
        const uint32_t aAh = b + relA,            aAl = b + REGB + relA;
        const uint32_t aBh = b + 2 * REGB + relB, aBl = b + 3 * REGB + relB;

#pragma unroll
        for (int ks = 0; ks < 2; ++ks) {
            const uint32_t ko = ks * 32;
            uint32_t bhf[8][2], blf[8][2];
#pragma unroll
            for (int p = 0; p < 4; ++p) {
                ldm4(aBh + p * (16 * TAS * 2) + ko,
                     bhf[2*p][0], bhf[2*p][1], bhf[2*p+1][0], bhf[2*p+1][1]);
                ldm4(aBl + p * (16 * TAS * 2) + ko,
                     blf[2*p][0], blf[2*p][1], blf[2*p+1][0], blf[2*p+1][1]);
            }
#pragma unroll
            for (int mi = 0; mi < 4; ++mi) {
                uint32_t ah[4], al[4];
                ldm4(aAh + mi * (16 * TAS * 2) + ko, ah[0], ah[1], ah[2], ah[3]);
                ldm4(aAl + mi * (16 * TAS * 2) + ko, al[0], al[1], al[2], al[3]);
#pragma unroll
                for (int ni = 0; ni < 8; ++ni) mma_bf16(c[mi][ni], ah, bhf[ni]);
#pragma unroll
                for (int ni = 0; ni < 8; ++ni) mma_bf16(c[mi][ni], ah, blf[ni]);
#pragma unroll
                for (int ni = 0; ni < 8; ++ni) mma_bf16(c[mi][ni], al, bhf[ni]);
            }
        }
        __syncthreads();
    }

#pragma unroll
    for (int mi = 0; mi < 4; ++mi) {
        const int row0 = bm + wm * 64 + mi * 16 + (lane >> 2);
#pragma unroll
        for (int ni = 0; ni < 8; ++ni) {
            const int col = bn + wn * 64 + ni * 8 + ((lane & 3) << 1);
            float v0 = c[mi][ni][0], v1 = c[mi][ni][1];
            float v2 = c[mi][ni][2], v3 = c[mi][ni][3];
            if (OUT == 0) {
                float2 a; a.x = v0; a.y = v1;
                float2 bq; bq.x = v2; bq.y = v3;
                *(float2*)&C[(size_t)row0 * N + col]       = a;
                *(float2*)&C[(size_t)(row0 + 8) * N + col] = bq;
            } else if (OUT == 1) {
                v0 = fmaxf(v0, 0.f); v1 = fmaxf(v1, 0.f);
                v2 = fmaxf(v2, 0.f); v3 = fmaxf(v3, 0.f);
                __nv_bfloat16 h0, h1, h2, h3, l0, l1, l2, l3;
                split2(v0, h0, l0); split2(v1, h1, l1);
                split2(v2, h2, l2); split2(v3, h3, l3);
                *(__nv_bfloat162*)&Ch[(size_t)row0 * N + col]       = __nv_bfloat162(h0, h1);
                *(__nv_bfloat162*)&Cl[(size_t)row0 * N + col]       = __nv_bfloat162(l0, l1);
                *(__nv_bfloat162*)&Ch[(size_t)(row0 + 8) * N + col] = __nv_bfloat162(h2, h3);
                *(__nv_bfloat162*)&Cl[(size_t)(row0 + 8) * N + col] = __nv_bfloat162(l2, l3);
            } else {
                *(__nv_bfloat162*)&Ch[(size_t)row0 * N + col] =
                    __nv_bfloat162(__float2bfloat16(v0), __float2bfloat16(v1));
                *(__nv_bfloat162*)&Ch[(size_t)(row0 + 8) * N + col] =
                    __nv_bfloat162(__float2bfloat16(v2), __float2bfloat16(v3));
            }
        }
    }
}

template <int OUT>
__global__ __launch_bounds__(128, 2)
void gemm_bf(const __nv_bfloat16* __restrict__ Agh, const __nv_bfloat16* __restrict__ Agl,
             const __nv_bfloat16* __restrict__ Bgh, const __nv_bfloat16* __restrict__ Bgl,
             float* __restrict__ C, __nv_bfloat16* __restrict__ Ch,
             __nv_bfloat16* __restrict__ Cl, int M, int N, int K)
{
    gemm_body<OUT>(Agh, Agl, Bgh, Bgl, C, Ch, Cl, M, N, K);
}

// fused QKV projection: grid.z selects {Q, K, V}; bf16 output
__global__ __launch_bounds__(128, 2)
void gemm_qkv(const __nv_bfloat16* __restrict__ A0h, const __nv_bfloat16* __restrict__ A0l,
              const __nv_bfloat16* __restrict__ A1h, const __nv_bfloat16* __restrict__ A1l,
              const __nv_bfloat16* __restrict__ A2h, const __nv_bfloat16* __restrict__ A2l,
              const __nv_bfloat16* __restrict__ W0h, const __nv_bfloat16* __restrict__ W0l,
              const __nv_bfloat16* __restrict__ W1h, const __nv_bfloat16* __restrict__ W1l,
              const __nv_bfloat16* __restrict__ W2h, const __nv_bfloat16* __restrict__ W2l,
              __nv_bfloat16* __restrict__ Cq, __nv_bfloat16* __restrict__ Ck,
              __nv_bfloat16* __restrict__ Cv)
{
    const __nv_bfloat16 *Ah, *Al, *Bh, *Bl;
    __nv_bfloat16* Co;
    if (blockIdx.z == 0)      { Ah = A0h; Al = A0l; Bh = W0h; Bl = W0l; Co = Cq; }
    else if (blockIdx.z == 1) { Ah = A1h; Al = A1l; Bh = W1h; Bl = W1l; Co = Ck; }
    else                      { Ah = A2h; Al = A2l; Bh = W2h; Bl = W2l; Co = Cv; }
    gemm_body<2>(Ah, Al, Bh, Bl, nullptr, Co, nullptr, MTOT, DMODEL, DMODEL);
}

// ---------------------------------------------------------------------------
// Tensor-core flash attention — bf16 in, V row-major + ldmatrix.trans for PV
// ---------------------------------------------------------------------------
#define FM  64
#define FN  64
#define FQS 264
#define FA_SMEM_BYTES (3 * FM * FQS * 2)    // 101376

extern __shared__ char fa_raw[];

__global__ __launch_bounds__(128, 2)
void flash_tc(const __nv_bfloat16* __restrict__ Q, const __nv_bfloat16* __restrict__ K,
              const __nv_bfloat16* __restrict__ V, float* __restrict__ O)
{
    __nv_bfloat16* Qs = (__nv_bfloat16*)fa_raw;
    __nv_bfloat16* Ks = Qs + FM * FQS;
    __nv_bfloat16* Vs = Ks + FN * FQS;

    const int tid  = threadIdx.x;
    const int lane = tid & 31;
    const int w    = tid >> 5;
    const int qbase = blockIdx.x * FM;
    const int h = blockIdx.y, b = blockIdx.z;
    const size_t bstride = (size_t)SEQ * DMODEL;
    const __nv_bfloat16* Qb = Q + b * bstride + h * GSZ;
    const __nv_bfloat16* Kb = K + b * bstride + h * GSZ;
    const __nv_bfloat16* Vb = V + b * bstride + h * GSZ;

    const int lmA = lane & 15;
    const int lkA = (lane >> 4) << 3;
    const int lnB = ((lane >> 4) & 1) * 8 + (lane & 7);
    const int lkB = ((lane >> 3) & 1) * 8;

    const uint32_t aQ = sptr(Qs) + (uint32_t)((w * 16 + lmA) * FQS + lkA) * 2;
    const uint32_t aK = sptr(Ks) + (uint32_t)(lnB * FQS + lkB) * 2;
    const uint32_t aV = sptr(Vs) + (uint32_t)((lane & 15) * FQS + (lane >> 4) * 8) * 2;

#pragma unroll
    for (int j = 0; j < 16; ++j) {
        const int idx = tid + j * 128;
        const int row = idx >> 5, c8 = idx & 31;
        const uint4 u = *(const uint4*)(Qb + (size_t)(qbase + row) * DMODEL + c8 * 8);
        *(uint4*)(Qs + row * FQS + c8 * 8) = u;
    }

    float mA = -1e30f, mB = -1e30f, lA = 0.f, lB = 0.f;
    float o[32][4];
#pragma unroll
    for (int f = 0; f < 32; ++f)
#pragma unroll
        for (int e = 0; e < 4; ++e) o[f][e] = 0.f;

    for (int kb = 0; kb < SEQ; kb += FN) {
        __syncthreads();
#pragma unroll
        for (int j = 0; j < 16; ++j) {
            const int idx = tid + j * 128;
            const int row = idx >> 5, c8 = idx & 31;
            const uint4 uk = *(const uint4*)(Kb + (size_t)(kb + row) * DMODEL + c8 * 8);
            *(uint4*)(Ks + row * FQS + c8 * 8) = uk;
            const uint4 uv = *(const uint4*)(Vb + (size_t)(kb + row) * DMODEL + c8 * 8);
            *(uint4*)(Vs + row * FQS + c8 * 8) = uv;
        }
        __syncthreads();

        float s[8][4];
#pragma unroll
        for (int f = 0; f < 8; ++f)
#pragma unroll
            for (int e = 0; e < 4; ++e) s[f][e] = 0.f;

#pragma unroll
        for (int ks = 0; ks < 16; ++ks) {
            uint32_t af[4];
            ldm4(aQ + ks * 32, af[0], af[1], af[2], af[3]);
#pragma unroll
            for (int g = 0; g < 4; ++g) {
                uint32_t b0[2], b1[2];
                ldm4(aK + (uint32_t)(g * 16 * FQS) * 2 + ks * 32,
                     b0[0], b0[1], b1[0], b1[1]);
                mma_bf16(s[2 * g],     af, b0);
                mma_bf16(s[2 * g + 1], af, b1);
            }
        }

        float mxA = -1e30f, mxB = -1e30f;
#pragma unroll
        for (int f = 0; f < 8; ++f) {
            mxA = fmaxf(mxA, fmaxf(s[f][0], s[f][1]));
            mxB = fmaxf(mxB, fmaxf(s[f][2], s[f][3]));
        }
        mxA = fmaxf(mxA, __shfl_xor_sync(0xffffffffu, mxA, 1));
        mxA = fmaxf(mxA, __shfl_xor_sync(0xffffffffu, mxA, 2));
        mxB = fmaxf(mxB, __shfl_xor_sync(0xffffffffu, mxB, 1));
        mxB = fmaxf(mxB, __shfl_xor_sync(0xffffffffu, mxB, 2));
        const float mnA = fmaxf(mA, mxA);
        const float mnB = fmaxf(mB, mxB);
        float sumA = 0.f, sumB = 0.f;
#pragma unroll
        for (int f = 0; f < 8; ++f) {
            s[f][0] = e2(s[f][0] - mnA); s[f][1] = e2(s[f][1] - mnA);
            s[f][2] = e2(s[f][2] - mnB); s[f][3] = e2(s[f][3] - mnB);
            sumA += s[f][0] + s[f][1];
            sumB += s[f][2] + s[f][3];
        }
        sumA += __shfl_xor_sync(0xffffffffu, sumA, 1);
        sumA += __shfl_xor_sync(0xffffffffu, sumA, 2);
        sumB += __shfl_xor_sync(0xffffffffu, sumB, 1);
        sumB += __shfl_xor_sync(0xffffffffu, sumB, 2);
        const float ccA = e2(mA - mnA);
        const float ccB = e2(mB - mnB);
        lA = lA * ccA + sumA; mA = mnA;
        lB = lB * ccB + sumB; mB = mnB;

#pragma unroll
        for (int f = 0; f < 32; ++f) {
            o[f][0] *= ccA; o[f][1] *= ccA;
            o[f][2] *= ccB; o[f][3] *= ccB;
        }

#pragma unroll
        for (int kf = 0; kf < 4; ++kf) {
            uint32_t ap[4];
            ap[0] = packbf(s[2 * kf][0],     s[2 * kf][1]);
            ap[1] = packbf(s[2 * kf][2],     s[2 * kf][3]);
            ap[2] = packbf(s[2 * kf + 1][0], s[2 * kf + 1][1]);
            ap[3] = packbf(s[2 * kf + 1][2], s[2 * kf + 1][3]);
            const uint32_t aVk = aV + (uint32_t)(kf * 16 * FQS) * 2;
#pragma unroll
            for (int g = 0; g < 16; ++g) {
                uint32_t b0[2], b1[2];
                ldm4t(aVk + g * 32, b0[0], b0[1], b1[0], b1[1]);
                mma_bf16(o[2 * g],     ap, b0);
                mma_bf16(o[2 * g + 1], ap, b1);
            }
        }
    }

    const float liA = 1.f / lA;
    const float liB = 1.f / lB;
    const int rowA = qbase + w * 16 + (lane >> 2);
    float* Ob = O + b * bstride + h * GSZ;
#pragma unroll
    for (int f = 0; f < 32; ++f) {
        const int col = f * 8 + ((lane & 3) << 1);
        float2 rA; rA.x = o[f][0] * liA; rA.y = o[f][1] * liA;
        float2 rB; rB.x = o[f][2] * liB; rB.y = o[f][3] * liB;
        *(float2*)&Ob[(size_t)rowA * DMODEL + col]       = rA;
        *(float2*)&Ob[(size_t)(rowA + 8) * DMODEL + col] = rB;
    }
}

// ---------------------------------------------------------------------------
// out = LayerNorm(X + R); optionally emit bf16 (hi, lo) split
// ---------------------------------------------------------------------------
__global__ __launch_bounds__(128)
void add_ln_kernel(const float* __restrict__ X, const float* __restrict__ R,
                   const float* __restrict__ g, const float* __restrict__ bt,
                   float eps, float* __restrict__ out,
                   __nv_bfloat16* __restrict__ oh, __nv_bfloat16* __restrict__ ol,
                   int doSplit)
{
    const int row = blockIdx.x;
    const int tid = threadIdx.x;
    float4 v = *(const float4*)(X + (size_t)row * DMODEL + tid * 4);
    const float4 rr = *(const float4*)(R + (size_t)row * DMODEL + tid * 4);
    v.x += rr.x; v.y += rr.y; v.z += rr.z; v.w += rr.w;
    float s  = v.x + v.y + v.z + v.w;
    float sq = v.x * v.x + v.y * v.y + v.z * v.z + v.w * v.w;
#pragma unroll
    for (int off = 16; off; off >>= 1) {
        s  += __shfl_xor_sync(0xffffffffu, s,  off);
        sq += __shfl_xor_sync(0xffffffffu, sq, off);
    }
    __shared__ float ssum[4], ssq[4];
    const int w = tid >> 5, l = tid & 31;
    if (l == 0) { ssum[w] = s; ssq[w] = sq; }
    __syncthreads();
    s  = ssum[0] + ssum[1] + ssum[2] + ssum[3];
    sq = ssq[0]  + ssq[1]  + ssq[2]  + ssq[3];
    const float mean = s * (1.f / DMODEL);
    const float var  = sq * (1.f / DMODEL) - mean * mean;
    const float rstd = rsqrtf(var + eps);
    const float4 gg = *(const float4*)(g  + tid * 4);
    const float4 bb = *(const float4*)(bt + tid * 4);
    float4 r;
    r.x = (v.x - mean) * rstd * gg.x + bb.x;
    r.y = (v.y - mean) * rstd * gg.y + bb.y;
    r.z = (v.z - mean) * rstd * gg.z + bb.z;
    r.w = (v.w - mean) * rstd * gg.w + bb.w;
    *(float4*)(out + (size_t)row * DMODEL + tid * 4) = r;
    if (doSplit) {
        __nv_bfloat16 h0, h1, h2, h3, l0, l1, l2, l3;
        split2(r.x, h0, l0); split2(r.y, h1, l1);
        split2(r.z, h2, l2); split2(r.w, h3, l3);
        const size_t o = (size_t)row * DMODEL + tid * 4;
        *(__nv_bfloat162*)(oh + o)     = __nv_bfloat162(h0, h1);
        *(__nv_bfloat162*)(oh + o + 2) = __nv_bfloat162(h2, h3);
        *(__nv_bfloat162*)(ol + o)     = __nv_bfloat162(l0, l1);
        *(__nv_bfloat162*)(ol + o + 2) = __nv_bfloat162(l2, l3);
    }
}

// ---------------------------------------------------------------------------
// host side — blocks 0 and 1 run concurrently on forked streams
// ---------------------------------------------------------------------------
extern "C" void kernel_launch(void* const* d_in, const int* in_sizes, int n_in,
                              void* d_out, int out_size)
{
    (void)in_sizes; (void)n_in; (void)out_size;
    const float* Fm   = (const float*)d_in[0];
    const float* Fs   = (const float*)d_in[1];
    const float* Fq   = (const float*)d_in[2];
    const float* Wq   = (const float*)d_in[3];
    const float* Wk   = (const float*)d_in[4];
    const float* Wv   = (const float*)d_in[5];
    const float* lng  = (const float*)d_in[6];
    const float* lnb  = (const float*)d_in[7];
    const float* w1   = (const float*)d_in[8];
    const float* w2   = (const float*)d_in[9];
    const float* flg  = (const float*)d_in[10];
    const float* flb  = (const float*)d_in[11];
    float* out = (float*)d_out;

    // streams/events created once (host resources, not device memory)
    static cudaStream_t s1 = nullptr;
    static cudaEvent_t evFork = nullptr, evJoin = nullptr;
    if (!s1) {
        cudaStreamCreateWithFlags(&s1, cudaStreamNonBlocking);
        cudaEventCreateWithFlags(&evFork, cudaEventDisableTiming);
        cudaEventCreateWithFlags(&evJoin, cudaEventDisableTiming);
    }
    cudaStream_t s0 = 0;   // default (capture) stream

    float *att, *x, *y, *att2, *x2, *y2, *css, *cqq;
    cudaGetSymbolAddress((void**)&att,  g_att);
    cudaGetSymbolAddress((void**)&x,    g_x);
    cudaGetSymbolAddress((void**)&y,    g_y);
    cudaGetSymbolAddress((void**)&att2, g_att2);
    cudaGetSymbolAddress((void**)&x2,   g_x2);
    cudaGetSymbolAddress((void**)&y2,   g_y2);
    cudaGetSymbolAddress((void**)&css,  g_css);
    cudaGetSymbolAddress((void**)&cqq,  g_cqq);

    __nv_bfloat16 *qb, *kb, *vb, *qb2, *kb2, *vb2;
    __nv_bfloat16 *wqh, *wql, *wkh, *wkl, *wvh, *wvl, *w1h, *w1l, *w2h, *w2l;
    __nv_bfloat16 *fmh, *fml, *fsh, *fsl, *fqh, *fql;
    __nv_bfloat16 *cssh, *cssl, *cqqh, *cqql;
    __nv_bfloat16 *xh, *xl, *xh2, *xl2, *hh, *hl, *hh2, *hl2;
    cudaGetSymbolAddress((void**)&qb,  g_qb);
    cudaGetSymbolAddress((void**)&kb,  g_kb);
    cudaGetSymbolAddress((void**)&vb,  g_vb);
    cudaGetSymbolAddress((void**)&qb2, g_qb2);
    cudaGetSymbolAddress((void**)&kb2, g_kb2);
    cudaGetSymbolAddress((void**)&vb2, g_vb2);
    cudaGetSymbolAddress((void**)&wqh, g_wqh); cudaGetSymbolAddress((void**)&wql, g_wql);
    cudaGetSymbolAddress((void**)&wkh, g_wkh); cudaGetSymbolAddress((void**)&wkl, g_wkl);
    cudaGetSymbolAddress((void**)&wvh, g_wvh); cudaGetSymbolAddress((void**)&wvl, g_wvl);
    cudaGetSymbolAddress((void**)&w1h, g_w1h); cudaGetSymbolAddress((void**)&w1l, g_w1l);
    cudaGetSymbolAddress((void**)&w2h, g_w2h); cudaGetSymbolAddress((void**)&w2l, g_w2l);
    cudaGetSymbolAddress((void**)&fmh, g_fmh); cudaGetSymbolAddress((void**)&fml, g_fml);
    cudaGetSymbolAddress((void**)&fsh, g_fsh); cudaGetSymbolAddress((void**)&fsl, g_fsl);
    cudaGetSymbolAddress((void**)&fqh, g_fqh); cudaGetSymbolAddress((void**)&fql, g_fql);
    cudaGetSymbolAddress((void**)&cssh, g_cssh); cudaGetSymbolAddress((void**)&cssl, g_cssl);
    cudaGetSymbolAddress((void**)&cqqh, g_cqqh); cudaGetSymbolAddress((void**)&cqql, g_cqql);
    cudaGetSymbolAddress((void**)&xh,  g_xh);  cudaGetSymbolAddress((void**)&xl,  g_xl);
    cudaGetSymbolAddress((void**)&xh2, g_xh2); cudaGetSymbolAddress((void**)&xl2, g_xl2);
    cudaGetSymbolAddress((void**)&hh,  g_hh);  cudaGetSymbolAddress((void**)&hl,  g_hl);
    cudaGetSymbolAddress((void**)&hh2, g_hh2); cudaGetSymbolAddress((void**)&hl2, g_hl2);

    cudaFuncSetAttribute(flash_tc, cudaFuncAttributeMaxDynamicSharedMemorySize,
                         FA_SMEM_BYTES);
    cudaFuncSetAttribute(gemm_bf<0>, cudaFuncAttributeMaxDynamicSharedMemorySize,
                         GEMM_SMEM);
    cudaFuncSetAttribute(gemm_bf<1>, cudaFuncAttributeMaxDynamicSharedMemorySize,
                         GEMM_SMEM);
    cudaFuncSetAttribute(gemm_qkv, cudaFuncAttributeMaxDynamicSharedMemorySize,
                         GEMM_SMEM);

    // fused preprocessing on s0; Wq pre-scaled by QSC
    split_in_kernel<<<(3 * SEG4 + 255) / 256, 256, 0, s0>>>(Fm, Fs, Fq);
    split_w_kernel<<<(WTOT4 + 255) / 256, 256, 0, s0>>>(Wq, Wk, Wv, w1, w2);

    const dim3 gqkv(DMODEL / TBN, MTOT / TBM, 3);
    const dim3 gp(DMODEL / TBN, MTOT / TBM);
    const dim3 gh(DHID / TBN,   MTOT / TBM);
    const dim3 ga(SEQ / FM, NHEADS, BATCH);

    auto run_block = [&](cudaStream_t st, int i,
                         const __nv_bfloat16* Qh, const __nv_bfloat16* Ql,
                         const __nv_bfloat16* Kh, const __nv_bfloat16* Kl,
                         const __nv_bfloat16* Vh, const __nv_bfloat16* Vl,
                         const float* Rp, float* op,
                         __nv_bfloat16* oph, __nv_bfloat16* opl, int splitOut,
                         __nv_bfloat16* sqb, __nv_bfloat16* skb, __nv_bfloat16* svb,
                         float* satt, float* sx, float* sy,
                         __nv_bfloat16* sxh, __nv_bfloat16* sxl,
                         __nv_bfloat16* shh, __nv_bfloat16* shl) {
        const size_t wOff  = (size_t)i * DMODEL * DMODEL;
        const size_t w1Off = (size_t)i * DHID * DMODEL;
        gemm_qkv<<<gqkv, 128, GEMM_SMEM, st>>>(Qh, Ql, Kh, Kl, Vh, Vl,
                                               wqh + wOff, wql + wOff,
                                               wkh + wOff, wkl + wOff,
                                               wvh + wOff, wvl + wOff,
                                               sqb, skb, svb);
        flash_tc<<<ga, 128, FA_SMEM_BYTES, st>>>(sqb, skb, svb, satt);
        add_ln_kernel<<<MTOT, 128, 0, st>>>(satt, Rp, lng + i * DMODEL,
                                            lnb + i * DMODEL, 1e-5f, sx, sxh, sxl, 1);
        gemm_bf<1><<<gh, 128, GEMM_SMEM, st>>>(sxh, sxl, w1h + w1Off, w1l + w1Off,
                                               nullptr, shh, shl, MTOT, DHID, DMODEL);
        gemm_bf<0><<<gp, 128, GEMM_SMEM, st>>>(shh, shl, w2h + w1Off, w2l + w1Off,
                                               sy, nullptr, nullptr, MTOT, DMODEL, DHID);
        add_ln_kernel<<<MTOT, 128, 0, st>>>(sy, sx, flg + i * DMODEL,
                                            flb + i * DMODEL, 1e-6f, op, oph, opl,
                                            splitOut);
    };

    // fork: s1 waits for preprocessing
    cudaEventRecord(evFork, s0);
    cudaStreamWaitEvent(s1, evFork, 0);

    // block 0 on s0, block 1 on s1 (independent, disjoint scratch)
    run_block(s0, 0, fsh, fsl, fsh, fsl, fmh, fml, Fm, css, cssh, cssl, 1,
              qb, kb, vb, att, x, y, xh, xl, hh, hl);
    run_block(s1, 1, fqh, fql, fqh, fql, fqh, fql, Fq, cqq, cqqh, cqql, 1,
              qb2, kb2, vb2, att2, x2, y2, xh2, xl2, hh2, hl2);

    // join: s0 waits for block 1
    cudaEventRecord(evJoin, s1);
    cudaStreamWaitEvent(s0, evJoin, 0);

    // block 2 on s0: csq = blk(2, cqq, Fs, css, css)
    run_block(s0, 2, cqqh, cqql, fsh, fsl, cssh, cssl, css, out, nullptr, nullptr, 0,
              qb, kb, vb, att, x, y, xh, xl, hh, hl);
}